// round 9
// baseline (speedup 1.0000x reference)
#include <cuda_runtime.h>
#include <cuda_fp16.h>
#include <cstdint>
#include <math.h>

// Problem constants
#define BATCH 4
#define SEQ   2048
#define DIM   768
#define HEADS 12
#define DHEAD 64
#define INNER 768
#define ROWS  (BATCH * SEQ)        // 8192
#define QKV_N (3 * INNER)          // 2304

// Scratch (allocation-free: __device__ globals) — all intermediates fp16
__device__ __align__(256) __half g_xn[ROWS * DIM];
__device__ __align__(256) __half g_qkv[ROWS * QKV_N];
__device__ __align__(256) __half g_attn[ROWS * INNER];
__device__ __align__(256) __half g_wtq[QKV_N * DIM];   // W_qkv^T [N,K]
__device__ __align__(256) __half g_wto[DIM * INNER];   // W_out^T [N,K]

// ---------------------------------------------------------------------------
// helpers (plain sm_80-era PTX — compiles for bare compute_103)
// ---------------------------------------------------------------------------
__device__ __forceinline__ uint32_t smem_u32(const void* p) {
    uint32_t a;
    asm("{ .reg .u64 t; cvta.to.shared.u64 t, %1; cvt.u32.u64 %0, t; }"
        : "=r"(a) : "l"(p));
    return a;
}

__device__ __forceinline__ void cp16(uint32_t dst, const void* src) {
    asm volatile("cp.async.cg.shared.global [%0], [%1], 16;"
                 :: "r"(dst), "l"(src));
}
#define CP_COMMIT() asm volatile("cp.async.commit_group;")
#define CP_WAIT0()  asm volatile("cp.async.wait_group 0;")
#define CP_WAIT1()  asm volatile("cp.async.wait_group 1;")

__device__ __forceinline__ void ldm4(uint32_t r[4], uint32_t a) {
    asm volatile("ldmatrix.sync.aligned.m8n8.x4.shared.b16 {%0,%1,%2,%3}, [%4];"
        : "=r"(r[0]), "=r"(r[1]), "=r"(r[2]), "=r"(r[3]) : "r"(a));
}
__device__ __forceinline__ void ldm4t(uint32_t r[4], uint32_t a) {
    asm volatile("ldmatrix.sync.aligned.m8n8.x4.trans.shared.b16 {%0,%1,%2,%3}, [%4];"
        : "=r"(r[0]), "=r"(r[1]), "=r"(r[2]), "=r"(r[3]) : "r"(a));
}

__device__ __forceinline__ void mma16(float c[4], const uint32_t a[4],
                                      uint32_t b0, uint32_t b1) {
    asm volatile(
        "mma.sync.aligned.m16n8k16.row.col.f32.f16.f16.f32 "
        "{%0,%1,%2,%3}, {%4,%5,%6,%7}, {%8,%9}, {%0,%1,%2,%3};"
        : "+f"(c[0]), "+f"(c[1]), "+f"(c[2]), "+f"(c[3])
        : "r"(a[0]), "r"(a[1]), "r"(a[2]), "r"(a[3]), "r"(b0), "r"(b1));
}

__device__ __forceinline__ float ex2(float x) {
    float r;
    asm("ex2.approx.f32 %0, %1;" : "=f"(r) : "f"(x));
    return r;
}

// ---------------------------------------------------------------------------
// Kernel 0: transpose W[K,N] -> Wt[N,K] (fp16 out)
// ---------------------------------------------------------------------------
__global__ __launch_bounds__(256) void transpose_k(
    const float* __restrict__ W, __half* __restrict__ Wt, int R, int Ccols)
{
    __shared__ float t[32][33];
    const int c0 = blockIdx.x * 32, r0 = blockIdx.y * 32;
    const int x = threadIdx.x & 31, y = threadIdx.x >> 5;
    #pragma unroll
    for (int i = 0; i < 32; i += 8)
        t[y + i][x] = W[(size_t)(r0 + y + i) * Ccols + c0 + x];
    __syncthreads();
    #pragma unroll
    for (int i = 0; i < 32; i += 8)
        Wt[(size_t)(c0 + y + i) * R + r0 + x] = __float2half_rn(t[x][y + i]);
}

// ---------------------------------------------------------------------------
// Kernel 1: LayerNorm (fp16 out)
// ---------------------------------------------------------------------------
__global__ __launch_bounds__(256) void ln_kernel(
    const float* __restrict__ x, const float* __restrict__ g,
    const float* __restrict__ b, __half* __restrict__ xn)
{
    const int row = blockIdx.x;
    const int tid = threadIdx.x;
    const float* xr = x + (size_t)row * DIM;

    float v0 = xr[tid];
    float v1 = xr[tid + 256];
    float v2 = xr[tid + 512];
    float s  = v0 + v1 + v2;
    float ss = v0 * v0 + v1 * v1 + v2 * v2;

    #pragma unroll
    for (int m = 16; m; m >>= 1) {
        s  += __shfl_xor_sync(0xffffffffu, s, m);
        ss += __shfl_xor_sync(0xffffffffu, ss, m);
    }
    __shared__ float shs[8], shss[8], stat[2];
    const int w = tid >> 5, l = tid & 31;
    if (l == 0) { shs[w] = s; shss[w] = ss; }
    __syncthreads();
    if (tid == 0) {
        float S = 0.f, SS = 0.f;
        #pragma unroll
        for (int i = 0; i < 8; i++) { S += shs[i]; SS += shss[i]; }
        float mean = S * (1.f / DIM);
        float var  = SS * (1.f / DIM) - mean * mean;
        stat[0] = mean;
        stat[1] = rsqrtf(var + 1e-5f);
    }
    __syncthreads();
    const float mean = stat[0], rstd = stat[1];
    __half* xo = xn + (size_t)row * DIM;
    xo[tid]       = __float2half_rn((v0 - mean) * rstd * g[tid]       + b[tid]);
    xo[tid + 256] = __float2half_rn((v1 - mean) * rstd * g[tid + 256] + b[tid + 256]);
    xo[tid + 512] = __float2half_rn((v2 - mean) * rstd * g[tid + 512] + b[tid + 512]);
}

// ---------------------------------------------------------------------------
// Kernel 2/4: fp16 mma GEMM.  C[M,N] = A[M,K] @ Bt[N,K]^T + bias
// Block 256x128, 8 warps (4m x 2n), warp tile 64x64, BK=32,
// 3-stage cp.async ring, ONE __syncthreads per K-chunk.  (At the measured
// HMMA throughput ceiling — unchanged from R8.)
// ---------------------------------------------------------------------------
#define GSTR 40
#define G_AS  (256 * GSTR)
#define G_BS  (128 * GSTR)
#define G_SMEM ((3 * G_AS + 3 * G_BS) * 2)   // 92160 bytes

__global__ __launch_bounds__(256) void gemm_h(
    const __half* __restrict__ A, const __half* __restrict__ Bt,
    const float* __restrict__ bias, void* __restrict__ Cout,
    int N, int K, int half_out)
{
    extern __shared__ __half gsm[];
    __half* As = gsm;
    __half* Bs = gsm + 3 * G_AS;

    const int tid  = threadIdx.x;
    const int lane = tid & 31;
    const int wid  = tid >> 5;
    const int wm = (wid & 3) * 64;
    const int wn = (wid >> 2) * 64;
    const int qr = lane >> 2, qc = lane & 3;
    const int bx = blockIdx.x, by = blockIdx.y;

    const __half* Ab = A  + (size_t)by * 256 * K;
    const __half* Bb = Bt + (size_t)bx * 128 * K;

    const int lr = tid >> 2;
    const int lc = (tid & 3) * 8;

    auto load_stage = [&](int st, int k0) {
        uint32_t au = smem_u32(As + st * G_AS);
        uint32_t bu = smem_u32(Bs + st * G_BS);
        #pragma unroll
        for (int j = 0; j < 4; j++) {
            const int r = lr + j * 64;
            cp16(au + (uint32_t)(r * GSTR + lc) * 2, Ab + (size_t)r * K + k0 + lc);
        }
        #pragma unroll
        for (int j = 0; j < 2; j++) {
            const int r = lr + j * 64;
            cp16(bu + (uint32_t)(r * GSTR + lc) * 2, Bb + (size_t)r * K + k0 + lc);
        }
        CP_COMMIT();
    };

    float acc[4][8][4];
    #pragma unroll
    for (int mi = 0; mi < 4; mi++)
        #pragma unroll
        for (int ni = 0; ni < 8; ni++)
            #pragma unroll
            for (int j = 0; j < 4; j++) acc[mi][ni][j] = 0.f;

    const int NC = K / 32;

    load_stage(0, 0);
    load_stage(1, 32);

    for (int kc = 0; kc < NC; kc++) {
        if (kc + 2 < NC) CP_WAIT1(); else CP_WAIT0();
        __syncthreads();
        if (kc + 2 < NC) load_stage((kc + 2) % 3, (kc + 2) * 32);

        const int st = kc % 3;
        const uint32_t a_base = smem_u32(As + st * G_AS);
        const uint32_t b_base = smem_u32(Bs + st * G_BS);

        #pragma unroll
        for (int ks = 0; ks < 2; ks++) {
            const int k0 = ks * 16;
            uint32_t af[4][4];
            #pragma unroll
            for (int mi = 0; mi < 4; mi++) {
                const uint32_t ad = a_base +
                    (uint32_t)((wm + mi * 16 + (lane & 15)) * GSTR
                               + k0 + ((lane >> 4) << 3)) * 2;
                ldm4(af[mi], ad);
            }
            #pragma unroll
            for (int np = 0; np < 4; np++) {
                uint32_t bf[4];
                const uint32_t bd = b_base +
                    (uint32_t)((wn + np * 16 + (lane & 7) + ((lane >> 4) << 3)) * GSTR
                               + k0 + (((lane >> 3) & 1) << 3)) * 2;
                ldm4(bf, bd);
                #pragma unroll
                for (int mi = 0; mi < 4; mi++) {
                    mma16(acc[mi][2 * np],     af[mi], bf[0], bf[1]);
                    mma16(acc[mi][2 * np + 1], af[mi], bf[2], bf[3]);
                }
            }
        }
    }

    const int cb = bx * 128 + wn;
    if (half_out) {
        __half* C = (__half*)Cout;
        #pragma unroll
        for (int mi = 0; mi < 4; mi++)
            #pragma unroll
            for (int hf = 0; hf < 2; hf++) {
                const int row = by * 256 + wm + mi * 16 + qr + hf * 8;
                __half* Cp = C + (size_t)row * N + cb;
                #pragma unroll
                for (int ni = 0; ni < 8; ni++) {
                    const int c = ni * 8 + 2 * qc;
                    *(__half2*)(Cp + c) = __floats2half2_rn(
                        acc[mi][ni][hf * 2 + 0] + bias[cb + c],
                        acc[mi][ni][hf * 2 + 1] + bias[cb + c + 1]);
                }
            }
    } else {
        float* C = (float*)Cout;
        #pragma unroll
        for (int mi = 0; mi < 4; mi++)
            #pragma unroll
            for (int hf = 0; hf < 2; hf++) {
                const int row = by * 256 + wm + mi * 16 + qr + hf * 8;
                float* Cp = C + (size_t)row * N + cb;
                #pragma unroll
                for (int ni = 0; ni < 8; ni++) {
                    const int c = ni * 8 + 2 * qc;
                    float2 v;
                    v.x = acc[mi][ni][hf * 2 + 0] + bias[cb + c];
                    v.y = acc[mi][ni][hf * 2 + 1] + bias[cb + c + 1];
                    *(float2*)(Cp + c) = v;
                }
            }
    }
}

// ---------------------------------------------------------------------------
// Kernel 3: fp16 flash attention.  BR=128, BC=128, d=64.  8 warps; each warp
// owns 16 query rows.  ONE online-softmax update per 128 keys (halved
// softmax overhead vs BC=64).  3-stage cp.async K/V ring, one sync per tile.
// ---------------------------------------------------------------------------
#define FSTR 72            // Q/K/V row stride (halfs), ≡8 mod 32
#define PSTR 136           // P row stride (halfs),   ≡8 mod 32
#define F_Q   (128 * FSTR)
#define F_P   (128 * PSTR)
#define F_KV  (128 * FSTR)
#define F_SMEM ((F_Q + F_P + 6 * F_KV) * 2)   // 163840 bytes
#define SC_L2E 0.18033688011112042f            // 0.125 * log2(e)

__global__ __launch_bounds__(256) void flash_h(
    const __half* __restrict__ qkv, __half* __restrict__ out)
{
    extern __shared__ __half fs[];
    __half* Qs = fs;                        // 128 x FSTR
    __half* Ps = fs + F_Q;                  // 128 x PSTR
    __half* Ks = fs + F_Q + F_P;            // 3 stages x 128 x FSTR
    __half* Vs = fs + F_Q + F_P + 3 * F_KV; // 3 stages x 128 x FSTR

    const int tid  = threadIdx.x;
    const int lane = tid & 31;
    const int wid  = tid >> 5;              // 0..7
    const int qr = lane >> 2, qc = lane & 3;
    const int m0 = wid * 16;

    const int qt = blockIdx.x;              // 0..15 (128-row query tiles)
    const int bh = blockIdx.y;              // 0..47
    const int bb = bh / HEADS, h = bh % HEADS;

    const __half* base = qkv + (size_t)bb * SEQ * QKV_N;
    const __half* qb = base + h * DHEAD;
    const __half* kb = base + INNER + h * DHEAD;
    const __half* vb = base + 2 * INNER + h * DHEAD;

    const uint32_t q_u = smem_u32(Qs);
    const uint32_t p_u = smem_u32(Ps);

    const int lr = tid >> 3;                // 0..31 loader row base
    const int lc8 = (tid & 7) * 8;

    // load one 128-key K/V stage (4 rows per thread per operand)
    auto load_kv = [&](int st, int t) {
        uint32_t ku = smem_u32(Ks + st * F_KV);
        uint32_t vu = smem_u32(Vs + st * F_KV);
        #pragma unroll
        for (int j = 0; j < 4; j++) {
            const int r = lr + j * 32;
            const size_t off = (size_t)(t * 128 + r) * QKV_N + lc8;
            cp16(ku + (uint32_t)(r * FSTR + lc8) * 2, kb + off);
            cp16(vu + (uint32_t)(r * FSTR + lc8) * 2, vb + off);
        }
        CP_COMMIT();
    };

    // prologue: group0 = Q + K/V stage0 ; group1 = K/V stage1
    #pragma unroll
    for (int j = 0; j < 4; j++) {
        const int r = lr + j * 32;
        cp16(q_u + (uint32_t)(r * FSTR + lc8) * 2,
             qb + (size_t)(qt * 128 + r) * QKV_N + lc8);
    }
    {
        uint32_t ku = smem_u32(Ks);
        uint32_t vu = smem_u32(Vs);
        #pragma unroll
        for (int j = 0; j < 4; j++) {
            const int r = lr + j * 32;
            const size_t off = (size_t)r * QKV_N + lc8;
            cp16(ku + (uint32_t)(r * FSTR + lc8) * 2, kb + off);
            cp16(vu + (uint32_t)(r * FSTR + lc8) * 2, vb + off);
        }
        CP_COMMIT();
    }
    load_kv(1, 1);

    float mrow[2] = {-1e30f, -1e30f};
    float lrow[2] = {0.f, 0.f};
    float o[8][4];
    #pragma unroll
    for (int ni = 0; ni < 8; ni++)
        #pragma unroll
        for (int j = 0; j < 4; j++) o[ni][j] = 0.f;

    uint32_t qf[4][4];
    const int NT = SEQ / 128;   // 16

    for (int t = 0; t < NT; t++) {
        if (t + 2 < NT) CP_WAIT1(); else CP_WAIT0();
        __syncthreads();
        if (t + 2 < NT) load_kv((t + 2) % 3, t + 2);

        const int st = t % 3;
        const uint32_t k_b = smem_u32(Ks + st * F_KV);
        const uint32_t v_b = smem_u32(Vs + st * F_KV);

        if (t == 0) {
            #pragma unroll
            for (int ks = 0; ks < 4; ks++)
                ldm4(qf[ks], q_u + (uint32_t)((m0 + (lane & 15)) * FSTR
                         + ks * 16 + ((lane >> 4) << 3)) * 2);
        }

        // ---- S = Q @ K^T  (16 x 128) ----
        float s[16][4];
        #pragma unroll
        for (int ni = 0; ni < 16; ni++)
            #pragma unroll
            for (int j = 0; j < 4; j++) s[ni][j] = 0.f;

        #pragma unroll
        for (int ks = 0; ks < 4; ks++) {
            const int k0 = ks * 16;
            #pragma unroll
            for (int np = 0; np < 8; np++) {
                uint32_t bf[4];
                const uint32_t bd = k_b +
                    (uint32_t)((np * 16 + (lane & 7) + ((lane >> 4) << 3)) * FSTR
                               + k0 + (((lane >> 3) & 1) << 3)) * 2;
                ldm4(bf, bd);
                mma16(s[2 * np],     qf[ks], bf[0], bf[1]);
                mma16(s[2 * np + 1], qf[ks], bf[2], bf[3]);
            }
        }

        // ---- online softmax in exp2 domain, ONCE per 128 keys ----
        #pragma unroll
        for (int ni = 0; ni < 16; ni++)
            #pragma unroll
            for (int j = 0; j < 4; j++) s[ni][j] *= SC_L2E;

        float mx0 = -1e30f, mx1 = -1e30f;
        #pragma unroll
        for (int ni = 0; ni < 16; ni++) {
            mx0 = fmaxf(mx0, fmaxf(s[ni][0], s[ni][1]));
            mx1 = fmaxf(mx1, fmaxf(s[ni][2], s[ni][3]));
        }
        mx0 = fmaxf(mx0, __shfl_xor_sync(0xffffffffu, mx0, 1));
        mx0 = fmaxf(mx0, __shfl_xor_sync(0xffffffffu, mx0, 2));
        mx1 = fmaxf(mx1, __shfl_xor_sync(0xffffffffu, mx1, 1));
        mx1 = fmaxf(mx1, __shfl_xor_sync(0xffffffffu, mx1, 2));

        const float mn0 = fmaxf(mrow[0], mx0);
        const float mn1 = fmaxf(mrow[1], mx1);
        const float al0 = ex2(mrow[0] - mn0);
        const float al1 = ex2(mrow[1] - mn1);
        mrow[0] = mn0; mrow[1] = mn1;

        float sum0 = 0.f, sum1 = 0.f;
        #pragma unroll
        for (int ni = 0; ni < 16; ni++) {
            s[ni][0] = ex2(s[ni][0] - mn0); sum0 += s[ni][0];
            s[ni][1] = ex2(s[ni][1] - mn0); sum0 += s[ni][1];
            s[ni][2] = ex2(s[ni][2] - mn1); sum1 += s[ni][2];
            s[ni][3] = ex2(s[ni][3] - mn1); sum1 += s[ni][3];
        }
        sum0 += __shfl_xor_sync(0xffffffffu, sum0, 1);
        sum0 += __shfl_xor_sync(0xffffffffu, sum0, 2);
        sum1 += __shfl_xor_sync(0xffffffffu, sum1, 1);
        sum1 += __shfl_xor_sync(0xffffffffu, sum1, 2);
        lrow[0] = lrow[0] * al0 + sum0;
        lrow[1] = lrow[1] * al1 + sum1;

        #pragma unroll
        for (int ni = 0; ni < 8; ni++) {
            o[ni][0] *= al0; o[ni][1] *= al0;
            o[ni][2] *= al1; o[ni][3] *= al1;
        }

        // ---- P (C-frag fp32) -> warp-private SMEM rows as fp16 ----
        #pragma unroll
        for (int ni = 0; ni < 16; ni++) {
            const int c = ni * 8 + 2 * qc;
            *(__half2*)(Ps + (m0 + qr) * PSTR + c) =
                __floats2half2_rn(s[ni][0], s[ni][1]);
            *(__half2*)(Ps + (m0 + qr + 8) * PSTR + c) =
                __floats2half2_rn(s[ni][2], s[ni][3]);
        }
        __syncwarp();

        // ---- O += P @ V  (K-dim = 128; V via ldmatrix.trans) ----
        #pragma unroll
        for (int ks = 0; ks < 8; ks++) {
            uint32_t pf[4];
            ldm4(pf, p_u + (uint32_t)((m0 + (lane & 15)) * PSTR
                     + ks * 16 + ((lane >> 4) << 3)) * 2);
            #pragma unroll
            for (int np = 0; np < 4; np++) {
                uint32_t vf[4];
                const uint32_t vd = v_b +
                    (uint32_t)((ks * 16 + (lane & 7) + (((lane >> 3) & 1) << 3)) * FSTR
                               + np * 16 + ((lane >> 4) << 3)) * 2;
                ldm4t(vf, vd);
                mma16(o[2 * np],     pf, vf[0], vf[1]);
                mma16(o[2 * np + 1], pf, vf[2], vf[3]);
            }
        }
        __syncwarp();
    }

    // ---- normalize + store (half) into [b, n, h*64 + d] ----
    const float inv0 = 1.f / lrow[0];
    const float inv1 = 1.f / lrow[1];
    const size_t n0 = (size_t)bb * SEQ + qt * 128 + m0 + qr;
    #pragma unroll
    for (int ni = 0; ni < 8; ni++) {
        const int c = h * DHEAD + ni * 8 + 2 * qc;
        *(__half2*)(out + n0 * INNER + c) =
            __floats2half2_rn(o[ni][0] * inv0, o[ni][1] * inv0);
        *(__half2*)(out + (n0 + 8) * INNER + c) =
            __floats2half2_rn(o[ni][2] * inv1, o[ni][3] * inv1);
    }
}

// ---------------------------------------------------------------------------
extern "C" void kernel_launch(void* const* d_in, const int* in_sizes, int n_in,
                              void* d_out, int out_size)
{
    const float* x     = (const float*)d_in[0];
    const float* ln_g  = (const float*)d_in[1];
    const float* ln_b  = (const float*)d_in[2];
    const float* W_qkv = (const float*)d_in[3];
    const float* b_qkv = (const float*)d_in[4];
    const float* W_out = (const float*)d_in[5];
    const float* b_out = (const float*)d_in[6];
    float* out = (float*)d_out;

    __half *xn, *qkv, *attn, *wtq, *wto;
    cudaGetSymbolAddress((void**)&xn,   g_xn);
    cudaGetSymbolAddress((void**)&qkv,  g_qkv);
    cudaGetSymbolAddress((void**)&attn, g_attn);
    cudaGetSymbolAddress((void**)&wtq,  g_wtq);
    cudaGetSymbolAddress((void**)&wto,  g_wto);

    cudaFuncSetAttribute(gemm_h, cudaFuncAttributeMaxDynamicSharedMemorySize,
                         G_SMEM);
    cudaFuncSetAttribute(flash_h, cudaFuncAttributeMaxDynamicSharedMemorySize,
                         F_SMEM);

    // 0) transpose weights to [N,K] fp16
    transpose_k<<<dim3(QKV_N / 32, DIM / 32), 256>>>(W_qkv, wtq, DIM, QKV_N);
    transpose_k<<<dim3(DIM / 32, INNER / 32), 256>>>(W_out, wto, INNER, DIM);

    // 1) LayerNorm -> fp16
    ln_kernel<<<ROWS, 256>>>(x, ln_g, ln_b, xn);

    // 2) QKV projection (fp16 mma, half out)
    gemm_h<<<dim3(QKV_N / 128, ROWS / 256), 256, G_SMEM>>>(
        xn, wtq, b_qkv, qkv, QKV_N, DIM, 1);

    // 3) attention (fp16 flash, BC=128, half out)
    flash_h<<<dim3(SEQ / 128, BATCH * HEADS), 256, F_SMEM>>>(qkv, attn);

    // 4) output projection (fp16 mma, fp32 out)
    gemm_h<<<dim3(DIM / 128, ROWS / 256), 256, G_SMEM>>>(
        attn, wto, b_out, out, DIM, INNER, 0);
}

// round 10
// speedup vs baseline: 1.1455x; 1.1455x over previous
#include <cuda_runtime.h>
#include <cuda_fp16.h>
#include <cstdint>
#include <math.h>

// Problem constants
#define BATCH 4
#define SEQ   2048
#define DIM   768
#define HEADS 12
#define DHEAD 64
#define INNER 768
#define ROWS  (BATCH * SEQ)        // 8192
#define QKV_N (3 * INNER)          // 2304

// Scratch (allocation-free: __device__ globals) — all intermediates fp16
__device__ __align__(256) __half g_xn[ROWS * DIM];
__device__ __align__(256) __half g_qkv[ROWS * QKV_N];
__device__ __align__(256) __half g_attn[ROWS * INNER];
__device__ __align__(256) __half g_wtq[QKV_N * DIM];   // W_qkv^T [N,K]
__device__ __align__(256) __half g_wto[DIM * INNER];   // W_out^T [N,K]

// ---------------------------------------------------------------------------
// helpers (plain sm_80-era PTX — compiles for bare compute_103)
// ---------------------------------------------------------------------------
__device__ __forceinline__ uint32_t smem_u32(const void* p) {
    uint32_t a;
    asm("{ .reg .u64 t; cvta.to.shared.u64 t, %1; cvt.u32.u64 %0, t; }"
        : "=r"(a) : "l"(p));
    return a;
}

__device__ __forceinline__ void cp16(uint32_t dst, const void* src) {
    asm volatile("cp.async.cg.shared.global [%0], [%1], 16;"
                 :: "r"(dst), "l"(src));
}
#define CP_COMMIT() asm volatile("cp.async.commit_group;")
#define CP_WAIT0()  asm volatile("cp.async.wait_group 0;")
#define CP_WAIT1()  asm volatile("cp.async.wait_group 1;")

__device__ __forceinline__ void ldm4(uint32_t r[4], uint32_t a) {
    asm volatile("ldmatrix.sync.aligned.m8n8.x4.shared.b16 {%0,%1,%2,%3}, [%4];"
        : "=r"(r[0]), "=r"(r[1]), "=r"(r[2]), "=r"(r[3]) : "r"(a));
}
__device__ __forceinline__ void ldm4t(uint32_t r[4], uint32_t a) {
    asm volatile("ldmatrix.sync.aligned.m8n8.x4.trans.shared.b16 {%0,%1,%2,%3}, [%4];"
        : "=r"(r[0]), "=r"(r[1]), "=r"(r[2]), "=r"(r[3]) : "r"(a));
}

__device__ __forceinline__ void mma16(float c[4], const uint32_t a[4],
                                      uint32_t b0, uint32_t b1) {
    asm volatile(
        "mma.sync.aligned.m16n8k16.row.col.f32.f16.f16.f32 "
        "{%0,%1,%2,%3}, {%4,%5,%6,%7}, {%8,%9}, {%0,%1,%2,%3};"
        : "+f"(c[0]), "+f"(c[1]), "+f"(c[2]), "+f"(c[3])
        : "r"(a[0]), "r"(a[1]), "r"(a[2]), "r"(a[3]), "r"(b0), "r"(b1));
}

__device__ __forceinline__ float ex2(float x) {
    float r;
    asm("ex2.approx.f32 %0, %1;" : "=f"(r) : "f"(x));
    return r;
}

// ---------------------------------------------------------------------------
// Kernel 0: merged transpose of both weight matrices -> fp16 [N,K]
// z=0: W_qkv [768 x 2304];  z=1: W_out [768 x 768]
// ---------------------------------------------------------------------------
__global__ __launch_bounds__(256) void transpose_both(
    const float* __restrict__ Wq, __half* __restrict__ WqT,
    const float* __restrict__ Wo, __half* __restrict__ WoT)
{
    const int which = blockIdx.z;
    const int Ccols = which ? DIM : QKV_N;
    const int R     = DIM;                    // rows of W (= K)
    const float* W  = which ? Wo  : Wq;
    __half* Wt      = which ? WoT : WqT;

    const int c0 = blockIdx.x * 32, r0 = blockIdx.y * 32;
    if (c0 >= Ccols) return;

    __shared__ float t[32][33];
    const int x = threadIdx.x & 31, y = threadIdx.x >> 5;
    #pragma unroll
    for (int i = 0; i < 32; i += 8)
        t[y + i][x] = W[(size_t)(r0 + y + i) * Ccols + c0 + x];
    __syncthreads();
    #pragma unroll
    for (int i = 0; i < 32; i += 8)
        Wt[(size_t)(c0 + y + i) * R + r0 + x] = __float2half_rn(t[x][y + i]);
}

// ---------------------------------------------------------------------------
// Kernel 1: LayerNorm (fp16 out)
// ---------------------------------------------------------------------------
__global__ __launch_bounds__(256) void ln_kernel(
    const float* __restrict__ x, const float* __restrict__ g,
    const float* __restrict__ b, __half* __restrict__ xn)
{
    const int row = blockIdx.x;
    const int tid = threadIdx.x;
    const float* xr = x + (size_t)row * DIM;

    float v0 = xr[tid];
    float v1 = xr[tid + 256];
    float v2 = xr[tid + 512];
    float s  = v0 + v1 + v2;
    float ss = v0 * v0 + v1 * v1 + v2 * v2;

    #pragma unroll
    for (int m = 16; m; m >>= 1) {
        s  += __shfl_xor_sync(0xffffffffu, s, m);
        ss += __shfl_xor_sync(0xffffffffu, ss, m);
    }
    __shared__ float shs[8], shss[8], stat[2];
    const int w = tid >> 5, l = tid & 31;
    if (l == 0) { shs[w] = s; shss[w] = ss; }
    __syncthreads();
    if (tid == 0) {
        float S = 0.f, SS = 0.f;
        #pragma unroll
        for (int i = 0; i < 8; i++) { S += shs[i]; SS += shss[i]; }
        float mean = S * (1.f / DIM);
        float var  = SS * (1.f / DIM) - mean * mean;
        stat[0] = mean;
        stat[1] = rsqrtf(var + 1e-5f);
    }
    __syncthreads();
    const float mean = stat[0], rstd = stat[1];
    __half* xo = xn + (size_t)row * DIM;
    xo[tid]       = __float2half_rn((v0 - mean) * rstd * g[tid]       + b[tid]);
    xo[tid + 256] = __float2half_rn((v1 - mean) * rstd * g[tid + 256] + b[tid + 256]);
    xo[tid + 512] = __float2half_rn((v2 - mean) * rstd * g[tid + 512] + b[tid + 512]);
}

// ---------------------------------------------------------------------------
// Kernel 2/4: fp16 mma GEMM (R8 config — fastest measured: 117.9 µs QKV).
// Block 256x128, 8 warps (4m x 2n), warp tile 64x64, BK=32,
// 3-stage cp.async ring, ONE __syncthreads per K-chunk.
// ---------------------------------------------------------------------------
#define GSTR 40
#define G_AS  (256 * GSTR)
#define G_BS  (128 * GSTR)
#define G_SMEM ((3 * G_AS + 3 * G_BS) * 2)   // 92160 bytes

__global__ __launch_bounds__(256) void gemm_h(
    const __half* __restrict__ A, const __half* __restrict__ Bt,
    const float* __restrict__ bias, void* __restrict__ Cout,
    int N, int K, int half_out)
{
    extern __shared__ __half gsm[];
    __half* As = gsm;
    __half* Bs = gsm + 3 * G_AS;

    const int tid  = threadIdx.x;
    const int lane = tid & 31;
    const int wid  = tid >> 5;
    const int wm = (wid & 3) * 64;
    const int wn = (wid >> 2) * 64;
    const int qr = lane >> 2, qc = lane & 3;
    const int bx = blockIdx.x, by = blockIdx.y;

    const __half* Ab = A  + (size_t)by * 256 * K;
    const __half* Bb = Bt + (size_t)bx * 128 * K;

    const int lr = tid >> 2;
    const int lc = (tid & 3) * 8;

    auto load_stage = [&](int st, int k0) {
        uint32_t au = smem_u32(As + st * G_AS);
        uint32_t bu = smem_u32(Bs + st * G_BS);
        #pragma unroll
        for (int j = 0; j < 4; j++) {
            const int r = lr + j * 64;
            cp16(au + (uint32_t)(r * GSTR + lc) * 2, Ab + (size_t)r * K + k0 + lc);
        }
        #pragma unroll
        for (int j = 0; j < 2; j++) {
            const int r = lr + j * 64;
            cp16(bu + (uint32_t)(r * GSTR + lc) * 2, Bb + (size_t)r * K + k0 + lc);
        }
        CP_COMMIT();
    };

    float acc[4][8][4];
    #pragma unroll
    for (int mi = 0; mi < 4; mi++)
        #pragma unroll
        for (int ni = 0; ni < 8; ni++)
            #pragma unroll
            for (int j = 0; j < 4; j++) acc[mi][ni][j] = 0.f;

    const int NC = K / 32;

    load_stage(0, 0);
    load_stage(1, 32);

    for (int kc = 0; kc < NC; kc++) {
        if (kc + 2 < NC) CP_WAIT1(); else CP_WAIT0();
        __syncthreads();
        if (kc + 2 < NC) load_stage((kc + 2) % 3, (kc + 2) * 32);

        const int st = kc % 3;
        const uint32_t a_base = smem_u32(As + st * G_AS);
        const uint32_t b_base = smem_u32(Bs + st * G_BS);

        #pragma unroll
        for (int ks = 0; ks < 2; ks++) {
            const int k0 = ks * 16;
            uint32_t af[4][4];
            #pragma unroll
            for (int mi = 0; mi < 4; mi++) {
                const uint32_t ad = a_base +
                    (uint32_t)((wm + mi * 16 + (lane & 15)) * GSTR
                               + k0 + ((lane >> 4) << 3)) * 2;
                ldm4(af[mi], ad);
            }
            #pragma unroll
            for (int np = 0; np < 4; np++) {
                uint32_t bf[4];
                const uint32_t bd = b_base +
                    (uint32_t)((wn + np * 16 + (lane & 7) + ((lane >> 4) << 3)) * GSTR
                               + k0 + (((lane >> 3) & 1) << 3)) * 2;
                ldm4(bf, bd);
                #pragma unroll
                for (int mi = 0; mi < 4; mi++) {
                    mma16(acc[mi][2 * np],     af[mi], bf[0], bf[1]);
                    mma16(acc[mi][2 * np + 1], af[mi], bf[2], bf[3]);
                }
            }
        }
    }

    const int cb = bx * 128 + wn;
    if (half_out) {
        __half* C = (__half*)Cout;
        #pragma unroll
        for (int mi = 0; mi < 4; mi++)
            #pragma unroll
            for (int hf = 0; hf < 2; hf++) {
                const int row = by * 256 + wm + mi * 16 + qr + hf * 8;
                __half* Cp = C + (size_t)row * N + cb;
                #pragma unroll
                for (int ni = 0; ni < 8; ni++) {
                    const int c = ni * 8 + 2 * qc;
                    *(__half2*)(Cp + c) = __floats2half2_rn(
                        acc[mi][ni][hf * 2 + 0] + bias[cb + c],
                        acc[mi][ni][hf * 2 + 1] + bias[cb + c + 1]);
                }
            }
    } else {
        float* C = (float*)Cout;
        #pragma unroll
        for (int mi = 0; mi < 4; mi++)
            #pragma unroll
            for (int hf = 0; hf < 2; hf++) {
                const int row = by * 256 + wm + mi * 16 + qr + hf * 8;
                float* Cp = C + (size_t)row * N + cb;
                #pragma unroll
                for (int ni = 0; ni < 8; ni++) {
                    const int c = ni * 8 + 2 * qc;
                    float2 v;
                    v.x = acc[mi][ni][hf * 2 + 0] + bias[cb + c];
                    v.y = acc[mi][ni][hf * 2 + 1] + bias[cb + c + 1];
                    *(float2*)(Cp + c) = v;
                }
            }
    }
}

// ---------------------------------------------------------------------------
// Kernel 3: fp16 flash attention (exact R7 config — best measured).
// BR=64, BC=64, d=64.  4 warps; warp owns 16 query rows (warp-local online
// softmax, exp2 domain).  2-stage cp.async K/V.  V via ldmatrix.trans.
// ---------------------------------------------------------------------------
#define FSTR 72
#define SC_L2E 0.18033688011112042f          // 0.125 * log2(e)

__global__ __launch_bounds__(128) void flash_h(
    const __half* __restrict__ qkv, __half* __restrict__ out)
{
    extern __shared__ __half fs[];
    __half* Qs = fs;
    __half* Ps = fs + 64 * FSTR;
    __half* Kst[2] = { fs + 2 * 64 * FSTR, fs + 3 * 64 * FSTR };
    __half* Vst[2] = { fs + 4 * 64 * FSTR, fs + 5 * 64 * FSTR };

    const int tid  = threadIdx.x;
    const int lane = tid & 31;
    const int wid  = tid >> 5;
    const int qr = lane >> 2, qc = lane & 3;
    const int m0 = wid * 16;

    const int qt = blockIdx.x;
    const int bh = blockIdx.y;
    const int bb = bh / HEADS, h = bh % HEADS;

    const __half* base = qkv + (size_t)bb * SEQ * QKV_N;
    const __half* qb = base + h * DHEAD;
    const __half* kb = base + INNER + h * DHEAD;
    const __half* vb = base + 2 * INNER + h * DHEAD;

    const uint32_t q_u = smem_u32(Qs);
    const uint32_t p_u = smem_u32(Ps);
    const uint32_t k_u[2] = { smem_u32(Kst[0]), smem_u32(Kst[1]) };
    const uint32_t v_u[2] = { smem_u32(Vst[0]), smem_u32(Vst[1]) };

    // prologue: Q tile + K/V stage 0 (one group)
    #pragma unroll
    for (int j = 0; j < 4; j++) {
        const int i = tid + j * 128;
        const int r = i >> 3, cg = (i & 7) * 8;
        cp16(q_u + (uint32_t)(r * FSTR + cg) * 2,
             qb + (size_t)(qt * 64 + r) * QKV_N + cg);
    }
    #pragma unroll
    for (int j = 0; j < 4; j++) {
        const int i = tid + j * 128;
        const int r = i >> 3, cg = (i & 7) * 8;
        const size_t off = (size_t)r * QKV_N + cg;
        cp16(k_u[0] + (uint32_t)(r * FSTR + cg) * 2, kb + off);
        cp16(v_u[0] + (uint32_t)(r * FSTR + cg) * 2, vb + off);
    }
    CP_COMMIT();

    float mrow[2] = {-1e30f, -1e30f};
    float lrow[2] = {0.f, 0.f};
    float o[8][4];
    #pragma unroll
    for (int ni = 0; ni < 8; ni++)
        #pragma unroll
        for (int j = 0; j < 4; j++) o[ni][j] = 0.f;

    uint32_t qf[4][4];
    const int NT = SEQ / 64;

    for (int t = 0; t < NT; t++) {
        const int buf = t & 1;
        if (t + 1 < NT) {
            #pragma unroll
            for (int j = 0; j < 4; j++) {
                const int i = tid + j * 128;
                const int r = i >> 3, cg = (i & 7) * 8;
                const size_t off = (size_t)((t + 1) * 64 + r) * QKV_N + cg;
                cp16(k_u[buf ^ 1] + (uint32_t)(r * FSTR + cg) * 2, kb + off);
                cp16(v_u[buf ^ 1] + (uint32_t)(r * FSTR + cg) * 2, vb + off);
            }
            CP_COMMIT();
            CP_WAIT1();
        } else {
            CP_WAIT0();
        }
        __syncthreads();

        if (t == 0) {
            #pragma unroll
            for (int ks = 0; ks < 4; ks++)
                ldm4(qf[ks], q_u + (uint32_t)((m0 + (lane & 15)) * FSTR
                         + ks * 16 + ((lane >> 4) << 3)) * 2);
        }

        // ---- S = Q @ K^T ----
        float s[8][4];
        #pragma unroll
        for (int ni = 0; ni < 8; ni++)
            #pragma unroll
            for (int j = 0; j < 4; j++) s[ni][j] = 0.f;

        #pragma unroll
        for (int ks = 0; ks < 4; ks++) {
            const int k0 = ks * 16;
            #pragma unroll
            for (int np = 0; np < 4; np++) {
                uint32_t bf[4];
                const uint32_t bd = k_u[buf] +
                    (uint32_t)((np * 16 + (lane & 7) + ((lane >> 4) << 3)) * FSTR
                               + k0 + (((lane >> 3) & 1) << 3)) * 2;
                ldm4(bf, bd);
                mma16(s[2 * np],     qf[ks], bf[0], bf[1]);
                mma16(s[2 * np + 1], qf[ks], bf[2], bf[3]);
            }
        }

        // ---- online softmax in exp2 domain ----
        #pragma unroll
        for (int ni = 0; ni < 8; ni++)
            #pragma unroll
            for (int j = 0; j < 4; j++) s[ni][j] *= SC_L2E;

        float mx0 = -1e30f, mx1 = -1e30f;
        #pragma unroll
        for (int ni = 0; ni < 8; ni++) {
            mx0 = fmaxf(mx0, fmaxf(s[ni][0], s[ni][1]));
            mx1 = fmaxf(mx1, fmaxf(s[ni][2], s[ni][3]));
        }
        mx0 = fmaxf(mx0, __shfl_xor_sync(0xffffffffu, mx0, 1));
        mx0 = fmaxf(mx0, __shfl_xor_sync(0xffffffffu, mx0, 2));
        mx1 = fmaxf(mx1, __shfl_xor_sync(0xffffffffu, mx1, 1));
        mx1 = fmaxf(mx1, __shfl_xor_sync(0xffffffffu, mx1, 2));

        const float mn0 = fmaxf(mrow[0], mx0);
        const float mn1 = fmaxf(mrow[1], mx1);
        const float al0 = ex2(mrow[0] - mn0);
        const float al1 = ex2(mrow[1] - mn1);
        mrow[0] = mn0; mrow[1] = mn1;

        float sum0 = 0.f, sum1 = 0.f;
        #pragma unroll
        for (int ni = 0; ni < 8; ni++) {
            s[ni][0] = ex2(s[ni][0] - mn0); sum0 += s[ni][0];
            s[ni][1] = ex2(s[ni][1] - mn0); sum0 += s[ni][1];
            s[ni][2] = ex2(s[ni][2] - mn1); sum1 += s[ni][2];
            s[ni][3] = ex2(s[ni][3] - mn1); sum1 += s[ni][3];
        }
        sum0 += __shfl_xor_sync(0xffffffffu, sum0, 1);
        sum0 += __shfl_xor_sync(0xffffffffu, sum0, 2);
        sum1 += __shfl_xor_sync(0xffffffffu, sum1, 1);
        sum1 += __shfl_xor_sync(0xffffffffu, sum1, 2);
        lrow[0] = lrow[0] * al0 + sum0;
        lrow[1] = lrow[1] * al1 + sum1;

        #pragma unroll
        for (int ni = 0; ni < 8; ni++) {
            o[ni][0] *= al0; o[ni][1] *= al0;
            o[ni][2] *= al1; o[ni][3] *= al1;
        }

        // ---- P (C-frag fp32) -> warp-private SMEM as fp16 ----
        #pragma unroll
        for (int ni = 0; ni < 8; ni++) {
            const int c = ni * 8 + 2 * qc;
            *(__half2*)(Ps + (m0 + qr) * FSTR + c) =
                __floats2half2_rn(s[ni][0], s[ni][1]);
            *(__half2*)(Ps + (m0 + qr + 8) * FSTR + c) =
                __floats2half2_rn(s[ni][2], s[ni][3]);
        }
        __syncwarp();

        // ---- O += P @ V  (V via ldmatrix.trans) ----
        #pragma unroll
        for (int ks = 0; ks < 4; ks++) {
            uint32_t pf[4];
            ldm4(pf, p_u + (uint32_t)((m0 + (lane & 15)) * FSTR
                     + ks * 16 + ((lane >> 4) << 3)) * 2);
            #pragma unroll
            for (int np = 0; np < 4; np++) {
                uint32_t vf[4];
                const uint32_t vd = v_u[buf] +
                    (uint32_t)((ks * 16 + (lane & 7) + (((lane >> 3) & 1) << 3)) * FSTR
                               + np * 16 + ((lane >> 4) << 3)) * 2;
                ldm4t(vf, vd);
                mma16(o[2 * np],     pf, vf[0], vf[1]);
                mma16(o[2 * np + 1], pf, vf[2], vf[3]);
            }
        }
        __syncwarp();
        __syncthreads();   // protect K/V buf against next prefetch overwrite
    }

    // ---- normalize + store (half) into [b, n, h*64 + d] ----
    const float inv0 = 1.f / lrow[0];
    const float inv1 = 1.f / lrow[1];
    const size_t n0 = (size_t)bb * SEQ + qt * 64 + m0 + qr;
    #pragma unroll
    for (int ni = 0; ni < 8; ni++) {
        const int c = h * DHEAD + ni * 8 + 2 * qc;
        *(__half2*)(out + n0 * INNER + c) =
            __floats2half2_rn(o[ni][0] * inv0, o[ni][1] * inv0);
        *(__half2*)(out + (n0 + 8) * INNER + c) =
            __floats2half2_rn(o[ni][2] * inv1, o[ni][3] * inv1);
    }
}

// ---------------------------------------------------------------------------
extern "C" void kernel_launch(void* const* d_in, const int* in_sizes, int n_in,
                              void* d_out, int out_size)
{
    const float* x     = (const float*)d_in[0];
    const float* ln_g  = (const float*)d_in[1];
    const float* ln_b  = (const float*)d_in[2];
    const float* W_qkv = (const float*)d_in[3];
    const float* b_qkv = (const float*)d_in[4];
    const float* W_out = (const float*)d_in[5];
    const float* b_out = (const float*)d_in[6];
    float* out = (float*)d_out;

    __half *xn, *qkv, *attn, *wtq, *wto;
    cudaGetSymbolAddress((void**)&xn,   g_xn);
    cudaGetSymbolAddress((void**)&qkv,  g_qkv);
    cudaGetSymbolAddress((void**)&attn, g_attn);
    cudaGetSymbolAddress((void**)&wtq,  g_wtq);
    cudaGetSymbolAddress((void**)&wto,  g_wto);

    const int flash_smem = 6 * 64 * FSTR * (int)sizeof(__half);  // 55296
    cudaFuncSetAttribute(gemm_h, cudaFuncAttributeMaxDynamicSharedMemorySize,
                         G_SMEM);
    cudaFuncSetAttribute(flash_h, cudaFuncAttributeMaxDynamicSharedMemorySize,
                         flash_smem);

    // 0) both weight transposes in one launch
    transpose_both<<<dim3(QKV_N / 32, DIM / 32, 2), 256>>>(
        W_qkv, wtq, W_out, wto);

    // 1) LayerNorm -> fp16
    ln_kernel<<<ROWS, 256>>>(x, ln_g, ln_b, xn);

    // 2) QKV projection (fp16 mma, half out)
    gemm_h<<<dim3(QKV_N / 128, ROWS / 256), 256, G_SMEM>>>(
        xn, wtq, b_qkv, qkv, QKV_N, DIM, 1);

    // 3) attention (fp16 flash, R7 config, half out)
    flash_h<<<dim3(SEQ / 64, BATCH * HEADS), 128, flash_smem>>>(qkv, attn);

    // 4) output projection (fp16 mma, fp32 out)
    gemm_h<<<dim3(DIM / 128, ROWS / 256), 256, G_SMEM>>>(
        attn, wto, b_out, out, DIM, INNER, 0);
}

// round 11
// speedup vs baseline: 1.1575x; 1.0105x over previous
#include <cuda_runtime.h>
#include <cuda_fp16.h>
#include <cstdint>
#include <math.h>

// Problem constants
#define BATCH 4
#define SEQ   2048
#define DIM   768
#define HEADS 12
#define DHEAD 64
#define INNER 768
#define ROWS  (BATCH * SEQ)        // 8192
#define QKV_N (3 * INNER)          // 2304

// Scratch (allocation-free: __device__ globals) — all intermediates fp16
__device__ __align__(256) __half g_xn[ROWS * DIM];
__device__ __align__(256) __half g_qkv[ROWS * QKV_N];
__device__ __align__(256) __half g_attn[ROWS * INNER];
__device__ __align__(256) __half g_wtq[QKV_N * DIM];   // W_qkv^T [N,K]
__device__ __align__(256) __half g_wto[DIM * INNER];   // W_out^T [N,K]

// ---------------------------------------------------------------------------
// helpers (plain sm_80-era PTX — compiles for bare compute_103)
// ---------------------------------------------------------------------------
__device__ __forceinline__ uint32_t smem_u32(const void* p) {
    uint32_t a;
    asm("{ .reg .u64 t; cvta.to.shared.u64 t, %1; cvt.u32.u64 %0, t; }"
        : "=r"(a) : "l"(p));
    return a;
}

__device__ __forceinline__ void cp16(uint32_t dst, const void* src) {
    asm volatile("cp.async.cg.shared.global [%0], [%1], 16;"
                 :: "r"(dst), "l"(src));
}
#define CP_COMMIT() asm volatile("cp.async.commit_group;")
#define CP_WAIT0()  asm volatile("cp.async.wait_group 0;")
#define CP_WAIT1()  asm volatile("cp.async.wait_group 1;")

__device__ __forceinline__ void ldm4(uint32_t r[4], uint32_t a) {
    asm volatile("ldmatrix.sync.aligned.m8n8.x4.shared.b16 {%0,%1,%2,%3}, [%4];"
        : "=r"(r[0]), "=r"(r[1]), "=r"(r[2]), "=r"(r[3]) : "r"(a));
}
__device__ __forceinline__ void ldm4t(uint32_t r[4], uint32_t a) {
    asm volatile("ldmatrix.sync.aligned.m8n8.x4.trans.shared.b16 {%0,%1,%2,%3}, [%4];"
        : "=r"(r[0]), "=r"(r[1]), "=r"(r[2]), "=r"(r[3]) : "r"(a));
}

__device__ __forceinline__ void mma16(float c[4], const uint32_t a[4],
                                      uint32_t b0, uint32_t b1) {
    asm volatile(
        "mma.sync.aligned.m16n8k16.row.col.f32.f16.f16.f32 "
        "{%0,%1,%2,%3}, {%4,%5,%6,%7}, {%8,%9}, {%0,%1,%2,%3};"
        : "+f"(c[0]), "+f"(c[1]), "+f"(c[2]), "+f"(c[3])
        : "r"(a[0]), "r"(a[1]), "r"(a[2]), "r"(a[3]), "r"(b0), "r"(b1));
}

__device__ __forceinline__ float ex2(float x) {
    float r;
    asm("ex2.approx.f32 %0, %1;" : "=f"(r) : "f"(x));
    return r;
}

// ---------------------------------------------------------------------------
// Kernel 0: merged transpose of both weight matrices -> fp16 [N,K]
// z=0: W_qkv [768 x 2304];  z=1: W_out [768 x 768]
// ---------------------------------------------------------------------------
__global__ __launch_bounds__(256) void transpose_both(
    const float* __restrict__ Wq, __half* __restrict__ WqT,
    const float* __restrict__ Wo, __half* __restrict__ WoT)
{
    const int which = blockIdx.z;
    const int Ccols = which ? DIM : QKV_N;
    const int R     = DIM;
    const float* W  = which ? Wo  : Wq;
    __half* Wt      = which ? WoT : WqT;

    const int c0 = blockIdx.x * 32, r0 = blockIdx.y * 32;
    if (c0 >= Ccols) return;

    __shared__ float t[32][33];
    const int x = threadIdx.x & 31, y = threadIdx.x >> 5;
    #pragma unroll
    for (int i = 0; i < 32; i += 8)
        t[y + i][x] = W[(size_t)(r0 + y + i) * Ccols + c0 + x];
    __syncthreads();
    #pragma unroll
    for (int i = 0; i < 32; i += 8)
        Wt[(size_t)(c0 + y + i) * R + r0 + x] = __float2half_rn(t[x][y + i]);
}

// ---------------------------------------------------------------------------
// Kernel 1: LayerNorm (fp16 out)
// ---------------------------------------------------------------------------
__global__ __launch_bounds__(256) void ln_kernel(
    const float* __restrict__ x, const float* __restrict__ g,
    const float* __restrict__ b, __half* __restrict__ xn)
{
    const int row = blockIdx.x;
    const int tid = threadIdx.x;
    const float* xr = x + (size_t)row * DIM;

    float v0 = xr[tid];
    float v1 = xr[tid + 256];
    float v2 = xr[tid + 512];
    float s  = v0 + v1 + v2;
    float ss = v0 * v0 + v1 * v1 + v2 * v2;

    #pragma unroll
    for (int m = 16; m; m >>= 1) {
        s  += __shfl_xor_sync(0xffffffffu, s, m);
        ss += __shfl_xor_sync(0xffffffffu, ss, m);
    }
    __shared__ float shs[8], shss[8], stat[2];
    const int w = tid >> 5, l = tid & 31;
    if (l == 0) { shs[w] = s; shss[w] = ss; }
    __syncthreads();
    if (tid == 0) {
        float S = 0.f, SS = 0.f;
        #pragma unroll
        for (int i = 0; i < 8; i++) { S += shs[i]; SS += shss[i]; }
        float mean = S * (1.f / DIM);
        float var  = SS * (1.f / DIM) - mean * mean;
        stat[0] = mean;
        stat[1] = rsqrtf(var + 1e-5f);
    }
    __syncthreads();
    const float mean = stat[0], rstd = stat[1];
    __half* xo = xn + (size_t)row * DIM;
    xo[tid]       = __float2half_rn((v0 - mean) * rstd * g[tid]       + b[tid]);
    xo[tid + 256] = __float2half_rn((v1 - mean) * rstd * g[tid + 256] + b[tid + 256]);
    xo[tid + 512] = __float2half_rn((v2 - mean) * rstd * g[tid + 512] + b[tid + 512]);
}

// ---------------------------------------------------------------------------
// Kernel 2/4: fp16 mma GEMM (R8 config — fastest measured).
// Block 256x128, 8 warps (4m x 2n), warp tile 64x64, BK=32,
// 3-stage cp.async ring, ONE __syncthreads per K-chunk.
// ---------------------------------------------------------------------------
#define GSTR 40
#define G_AS  (256 * GSTR)
#define G_BS  (128 * GSTR)
#define G_SMEM ((3 * G_AS + 3 * G_BS) * 2)   // 92160 bytes

__global__ __launch_bounds__(256) void gemm_h(
    const __half* __restrict__ A, const __half* __restrict__ Bt,
    const float* __restrict__ bias, void* __restrict__ Cout,
    int N, int K, int half_out)
{
    extern __shared__ __half gsm[];
    __half* As = gsm;
    __half* Bs = gsm + 3 * G_AS;

    const int tid  = threadIdx.x;
    const int lane = tid & 31;
    const int wid  = tid >> 5;
    const int wm = (wid & 3) * 64;
    const int wn = (wid >> 2) * 64;
    const int qr = lane >> 2, qc = lane & 3;
    const int bx = blockIdx.x, by = blockIdx.y;

    const __half* Ab = A  + (size_t)by * 256 * K;
    const __half* Bb = Bt + (size_t)bx * 128 * K;

    const int lr = tid >> 2;
    const int lc = (tid & 3) * 8;

    auto load_stage = [&](int st, int k0) {
        uint32_t au = smem_u32(As + st * G_AS);
        uint32_t bu = smem_u32(Bs + st * G_BS);
        #pragma unroll
        for (int j = 0; j < 4; j++) {
            const int r = lr + j * 64;
            cp16(au + (uint32_t)(r * GSTR + lc) * 2, Ab + (size_t)r * K + k0 + lc);
        }
        #pragma unroll
        for (int j = 0; j < 2; j++) {
            const int r = lr + j * 64;
            cp16(bu + (uint32_t)(r * GSTR + lc) * 2, Bb + (size_t)r * K + k0 + lc);
        }
        CP_COMMIT();
    };

    float acc[4][8][4];
    #pragma unroll
    for (int mi = 0; mi < 4; mi++)
        #pragma unroll
        for (int ni = 0; ni < 8; ni++)
            #pragma unroll
            for (int j = 0; j < 4; j++) acc[mi][ni][j] = 0.f;

    const int NC = K / 32;

    load_stage(0, 0);
    load_stage(1, 32);

    for (int kc = 0; kc < NC; kc++) {
        if (kc + 2 < NC) CP_WAIT1(); else CP_WAIT0();
        __syncthreads();
        if (kc + 2 < NC) load_stage((kc + 2) % 3, (kc + 2) * 32);

        const int st = kc % 3;
        const uint32_t a_base = smem_u32(As + st * G_AS);
        const uint32_t b_base = smem_u32(Bs + st * G_BS);

        #pragma unroll
        for (int ks = 0; ks < 2; ks++) {
            const int k0 = ks * 16;
            uint32_t af[4][4];
            #pragma unroll
            for (int mi = 0; mi < 4; mi++) {
                const uint32_t ad = a_base +
                    (uint32_t)((wm + mi * 16 + (lane & 15)) * GSTR
                               + k0 + ((lane >> 4) << 3)) * 2;
                ldm4(af[mi], ad);
            }
            #pragma unroll
            for (int np = 0; np < 4; np++) {
                uint32_t bf[4];
                const uint32_t bd = b_base +
                    (uint32_t)((wn + np * 16 + (lane & 7) + ((lane >> 4) << 3)) * GSTR
                               + k0 + (((lane >> 3) & 1) << 3)) * 2;
                ldm4(bf, bd);
                #pragma unroll
                for (int mi = 0; mi < 4; mi++) {
                    mma16(acc[mi][2 * np],     af[mi], bf[0], bf[1]);
                    mma16(acc[mi][2 * np + 1], af[mi], bf[2], bf[3]);
                }
            }
        }
    }

    const int cb = bx * 128 + wn;
    if (half_out) {
        __half* C = (__half*)Cout;
        #pragma unroll
        for (int mi = 0; mi < 4; mi++)
            #pragma unroll
            for (int hf = 0; hf < 2; hf++) {
                const int row = by * 256 + wm + mi * 16 + qr + hf * 8;
                __half* Cp = C + (size_t)row * N + cb;
                #pragma unroll
                for (int ni = 0; ni < 8; ni++) {
                    const int c = ni * 8 + 2 * qc;
                    *(__half2*)(Cp + c) = __floats2half2_rn(
                        acc[mi][ni][hf * 2 + 0] + bias[cb + c],
                        acc[mi][ni][hf * 2 + 1] + bias[cb + c + 1]);
                }
            }
    } else {
        float* C = (float*)Cout;
        #pragma unroll
        for (int mi = 0; mi < 4; mi++)
            #pragma unroll
            for (int hf = 0; hf < 2; hf++) {
                const int row = by * 256 + wm + mi * 16 + qr + hf * 8;
                float* Cp = C + (size_t)row * N + cb;
                #pragma unroll
                for (int ni = 0; ni < 8; ni++) {
                    const int c = ni * 8 + 2 * qc;
                    float2 v;
                    v.x = acc[mi][ni][hf * 2 + 0] + bias[cb + c];
                    v.y = acc[mi][ni][hf * 2 + 1] + bias[cb + c + 1];
                    *(float2*)(Cp + c) = v;
                }
            }
    }
}

// ---------------------------------------------------------------------------
// Kernel 3: fp16 flash attention.  BR=64, BC=64, d=64.  4 warps; warp owns
// 16 query rows.  P stays in REGISTERS: the fp32 C-fragment of S=QK^T is
// register-identical to the fp16 A-fragment of P@V (m16n8k16), so the SMEM
// round-trip + ldmatrix for P is eliminated.  2-stage cp.async K/V.
// ---------------------------------------------------------------------------
#define FSTR 72
#define SC_L2E 0.18033688011112042f          // 0.125 * log2(e)

__global__ __launch_bounds__(128) void flash_h(
    const __half* __restrict__ qkv, __half* __restrict__ out)
{
    extern __shared__ __half fs[];
    __half* Qs = fs;
    __half* Kst[2] = { fs + 1 * 64 * FSTR, fs + 2 * 64 * FSTR };
    __half* Vst[2] = { fs + 3 * 64 * FSTR, fs + 4 * 64 * FSTR };

    const int tid  = threadIdx.x;
    const int lane = tid & 31;
    const int wid  = tid >> 5;
    const int qr = lane >> 2, qc = lane & 3;
    const int m0 = wid * 16;

    const int qt = blockIdx.x;
    const int bh = blockIdx.y;
    const int bb = bh / HEADS, h = bh % HEADS;

    const __half* base = qkv + (size_t)bb * SEQ * QKV_N;
    const __half* qb = base + h * DHEAD;
    const __half* kb = base + INNER + h * DHEAD;
    const __half* vb = base + 2 * INNER + h * DHEAD;

    const uint32_t q_u = smem_u32(Qs);
    const uint32_t k_u[2] = { smem_u32(Kst[0]), smem_u32(Kst[1]) };
    const uint32_t v_u[2] = { smem_u32(Vst[0]), smem_u32(Vst[1]) };

    // prologue: Q tile + K/V stage 0 (one group)
    #pragma unroll
    for (int j = 0; j < 4; j++) {
        const int i = tid + j * 128;
        const int r = i >> 3, cg = (i & 7) * 8;
        cp16(q_u + (uint32_t)(r * FSTR + cg) * 2,
             qb + (size_t)(qt * 64 + r) * QKV_N + cg);
    }
    #pragma unroll
    for (int j = 0; j < 4; j++) {
        const int i = tid + j * 128;
        const int r = i >> 3, cg = (i & 7) * 8;
        const size_t off = (size_t)r * QKV_N + cg;
        cp16(k_u[0] + (uint32_t)(r * FSTR + cg) * 2, kb + off);
        cp16(v_u[0] + (uint32_t)(r * FSTR + cg) * 2, vb + off);
    }
    CP_COMMIT();

    float mrow[2] = {-1e30f, -1e30f};
    float lrow[2] = {0.f, 0.f};
    float o[8][4];
    #pragma unroll
    for (int ni = 0; ni < 8; ni++)
        #pragma unroll
        for (int j = 0; j < 4; j++) o[ni][j] = 0.f;

    uint32_t qf[4][4];
    const int NT = SEQ / 64;

    for (int t = 0; t < NT; t++) {
        const int buf = t & 1;
        if (t + 1 < NT) {
            #pragma unroll
            for (int j = 0; j < 4; j++) {
                const int i = tid + j * 128;
                const int r = i >> 3, cg = (i & 7) * 8;
                const size_t off = (size_t)((t + 1) * 64 + r) * QKV_N + cg;
                cp16(k_u[buf ^ 1] + (uint32_t)(r * FSTR + cg) * 2, kb + off);
                cp16(v_u[buf ^ 1] + (uint32_t)(r * FSTR + cg) * 2, vb + off);
            }
            CP_COMMIT();
            CP_WAIT1();
        } else {
            CP_WAIT0();
        }
        __syncthreads();

        if (t == 0) {
            #pragma unroll
            for (int ks = 0; ks < 4; ks++)
                ldm4(qf[ks], q_u + (uint32_t)((m0 + (lane & 15)) * FSTR
                         + ks * 16 + ((lane >> 4) << 3)) * 2);
        }

        // ---- S = Q @ K^T ----
        float s[8][4];
        #pragma unroll
        for (int ni = 0; ni < 8; ni++)
            #pragma unroll
            for (int j = 0; j < 4; j++) s[ni][j] = 0.f;

        #pragma unroll
        for (int ks = 0; ks < 4; ks++) {
            const int k0 = ks * 16;
            #pragma unroll
            for (int np = 0; np < 4; np++) {
                uint32_t bf[4];
                const uint32_t bd = k_u[buf] +
                    (uint32_t)((np * 16 + (lane & 7) + ((lane >> 4) << 3)) * FSTR
                               + k0 + (((lane >> 3) & 1) << 3)) * 2;
                ldm4(bf, bd);
                mma16(s[2 * np],     qf[ks], bf[0], bf[1]);
                mma16(s[2 * np + 1], qf[ks], bf[2], bf[3]);
            }
        }

        // ---- online softmax in exp2 domain ----
        #pragma unroll
        for (int ni = 0; ni < 8; ni++)
            #pragma unroll
            for (int j = 0; j < 4; j++) s[ni][j] *= SC_L2E;

        float mx0 = -1e30f, mx1 = -1e30f;
        #pragma unroll
        for (int ni = 0; ni < 8; ni++) {
            mx0 = fmaxf(mx0, fmaxf(s[ni][0], s[ni][1]));
            mx1 = fmaxf(mx1, fmaxf(s[ni][2], s[ni][3]));
        }
        mx0 = fmaxf(mx0, __shfl_xor_sync(0xffffffffu, mx0, 1));
        mx0 = fmaxf(mx0, __shfl_xor_sync(0xffffffffu, mx0, 2));
        mx1 = fmaxf(mx1, __shfl_xor_sync(0xffffffffu, mx1, 1));
        mx1 = fmaxf(mx1, __shfl_xor_sync(0xffffffffu, mx1, 2));

        const float mn0 = fmaxf(mrow[0], mx0);
        const float mn1 = fmaxf(mrow[1], mx1);
        const float al0 = ex2(mrow[0] - mn0);
        const float al1 = ex2(mrow[1] - mn1);
        mrow[0] = mn0; mrow[1] = mn1;

        float sum0 = 0.f, sum1 = 0.f;
        #pragma unroll
        for (int ni = 0; ni < 8; ni++) {
            s[ni][0] = ex2(s[ni][0] - mn0); sum0 += s[ni][0];
            s[ni][1] = ex2(s[ni][1] - mn0); sum0 += s[ni][1];
            s[ni][2] = ex2(s[ni][2] - mn1); sum1 += s[ni][2];
            s[ni][3] = ex2(s[ni][3] - mn1); sum1 += s[ni][3];
        }
        sum0 += __shfl_xor_sync(0xffffffffu, sum0, 1);
        sum0 += __shfl_xor_sync(0xffffffffu, sum0, 2);
        sum1 += __shfl_xor_sync(0xffffffffu, sum1, 1);
        sum1 += __shfl_xor_sync(0xffffffffu, sum1, 2);
        lrow[0] = lrow[0] * al0 + sum0;
        lrow[1] = lrow[1] * al1 + sum1;

        #pragma unroll
        for (int ni = 0; ni < 8; ni++) {
            o[ni][0] *= al0; o[ni][1] *= al0;
            o[ni][2] *= al1; o[ni][3] *= al1;
        }

        // ---- O += P @ V : P A-fragments built directly from S C-fragments
        //      (C(qr,2qc)/(qr+8,2qc) layout == A(a0/a1) layout; tiles 2ks,
        //       2ks+1 supply the a2/a3 halves).  No SMEM, no ldmatrix.
        #pragma unroll
        for (int ks = 0; ks < 4; ks++) {
            uint32_t pf[4];
            asm("cvt.rn.f16x2.f32 %0, %1, %2;" : "=r"(pf[0])
                : "f"(s[2 * ks][1]),     "f"(s[2 * ks][0]));
            asm("cvt.rn.f16x2.f32 %0, %1, %2;" : "=r"(pf[1])
                : "f"(s[2 * ks][3]),     "f"(s[2 * ks][2]));
            asm("cvt.rn.f16x2.f32 %0, %1, %2;" : "=r"(pf[2])
                : "f"(s[2 * ks + 1][1]), "f"(s[2 * ks + 1][0]));
            asm("cvt.rn.f16x2.f32 %0, %1, %2;" : "=r"(pf[3])
                : "f"(s[2 * ks + 1][3]), "f"(s[2 * ks + 1][2]));
            #pragma unroll
            for (int np = 0; np < 4; np++) {
                uint32_t vf[4];
                const uint32_t vd = v_u[buf] +
                    (uint32_t)((ks * 16 + (lane & 7) + (((lane >> 3) & 1) << 3)) * FSTR
                               + np * 16 + ((lane >> 4) << 3)) * 2;
                ldm4t(vf, vd);
                mma16(o[2 * np],     pf, vf[0], vf[1]);
                mma16(o[2 * np + 1], pf, vf[2], vf[3]);
            }
        }
        __syncthreads();   // protect K/V buf against next prefetch overwrite
    }

    // ---- normalize + store (half) into [b, n, h*64 + d] ----
    const float inv0 = 1.f / lrow[0];
    const float inv1 = 1.f / lrow[1];
    const size_t n0 = (size_t)bb * SEQ + qt * 64 + m0 + qr;
    #pragma unroll
    for (int ni = 0; ni < 8; ni++) {
        const int c = h * DHEAD + ni * 8 + 2 * qc;
        *(__half2*)(out + n0 * INNER + c) =
            __floats2half2_rn(o[ni][0] * inv0, o[ni][1] * inv0);
        *(__half2*)(out + (n0 + 8) * INNER + c) =
            __floats2half2_rn(o[ni][2] * inv1, o[ni][3] * inv1);
    }
}

// ---------------------------------------------------------------------------
extern "C" void kernel_launch(void* const* d_in, const int* in_sizes, int n_in,
                              void* d_out, int out_size)
{
    const float* x     = (const float*)d_in[0];
    const float* ln_g  = (const float*)d_in[1];
    const float* ln_b  = (const float*)d_in[2];
    const float* W_qkv = (const float*)d_in[3];
    const float* b_qkv = (const float*)d_in[4];
    const float* W_out = (const float*)d_in[5];
    const float* b_out = (const float*)d_in[6];
    float* out = (float*)d_out;

    __half *xn, *qkv, *attn, *wtq, *wto;
    cudaGetSymbolAddress((void**)&xn,   g_xn);
    cudaGetSymbolAddress((void**)&qkv,  g_qkv);
    cudaGetSymbolAddress((void**)&attn, g_attn);
    cudaGetSymbolAddress((void**)&wtq,  g_wtq);
    cudaGetSymbolAddress((void**)&wto,  g_wto);

    const int flash_smem = 5 * 64 * FSTR * (int)sizeof(__half);  // 46080
    cudaFuncSetAttribute(gemm_h, cudaFuncAttributeMaxDynamicSharedMemorySize,
                         G_SMEM);
    cudaFuncSetAttribute(flash_h, cudaFuncAttributeMaxDynamicSharedMemorySize,
                         flash_smem);

    // 0) both weight transposes in one launch
    transpose_both<<<dim3(QKV_N / 32, DIM / 32, 2), 256>>>(
        W_qkv, wtq, W_out, wto);

    // 1) LayerNorm -> fp16
    ln_kernel<<<ROWS, 256>>>(x, ln_g, ln_b, xn);

    // 2) QKV projection (fp16 mma, half out)
    gemm_h<<<dim3(QKV_N / 128, ROWS / 256), 256, G_SMEM>>>(
        xn, wtq, b_qkv, qkv, QKV_N, DIM, 1);

    // 3) attention (fp16 flash, register-resident P, half out)
    flash_h<<<dim3(SEQ / 64, BATCH * HEADS), 128, flash_smem>>>(qkv, attn);

    // 4) output projection (fp16 mma, fp32 out)
    gemm_h<<<dim3(DIM / 128, ROWS / 256), 256, G_SMEM>>>(
        attn, wto, b_out, out, DIM, INNER, 0);
}

// round 12
// speedup vs baseline: 1.1695x; 1.0104x over previous
#include <cuda_runtime.h>
#include <cuda_fp16.h>
#include <cstdint>
#include <math.h>

// Problem constants
#define BATCH 4
#define SEQ   2048
#define DIM   768
#define HEADS 12
#define DHEAD 64
#define INNER 768
#define ROWS  (BATCH * SEQ)        // 8192
#define QKV_N (3 * INNER)          // 2304

// Scratch (allocation-free: __device__ globals) — all intermediates fp16
__device__ __align__(256) __half g_xn[ROWS * DIM];
__device__ __align__(256) __half g_qkv[ROWS * QKV_N];
__device__ __align__(256) __half g_attn[ROWS * INNER];
__device__ __align__(256) __half g_wtq[QKV_N * DIM];   // W_qkv^T [N,K]
__device__ __align__(256) __half g_wto[DIM * INNER];   // W_out^T [N,K]

// ---------------------------------------------------------------------------
// helpers (plain sm_80-era PTX — compiles for bare compute_103)
// ---------------------------------------------------------------------------
__device__ __forceinline__ uint32_t smem_u32(const void* p) {
    uint32_t a;
    asm("{ .reg .u64 t; cvta.to.shared.u64 t, %1; cvt.u32.u64 %0, t; }"
        : "=r"(a) : "l"(p));
    return a;
}

__device__ __forceinline__ void cp16(uint32_t dst, const void* src) {
    asm volatile("cp.async.cg.shared.global [%0], [%1], 16;"
                 :: "r"(dst), "l"(src));
}
#define CP_COMMIT() asm volatile("cp.async.commit_group;")
#define CP_WAIT0()  asm volatile("cp.async.wait_group 0;")
#define CP_WAIT1()  asm volatile("cp.async.wait_group 1;")

__device__ __forceinline__ void ldm4(uint32_t r[4], uint32_t a) {
    asm volatile("ldmatrix.sync.aligned.m8n8.x4.shared.b16 {%0,%1,%2,%3}, [%4];"
        : "=r"(r[0]), "=r"(r[1]), "=r"(r[2]), "=r"(r[3]) : "r"(a));
}
__device__ __forceinline__ void ldm4t(uint32_t r[4], uint32_t a) {
    asm volatile("ldmatrix.sync.aligned.m8n8.x4.trans.shared.b16 {%0,%1,%2,%3}, [%4];"
        : "=r"(r[0]), "=r"(r[1]), "=r"(r[2]), "=r"(r[3]) : "r"(a));
}

__device__ __forceinline__ void mma16(float c[4], const uint32_t a[4],
                                      uint32_t b0, uint32_t b1) {
    asm volatile(
        "mma.sync.aligned.m16n8k16.row.col.f32.f16.f16.f32 "
        "{%0,%1,%2,%3}, {%4,%5,%6,%7}, {%8,%9}, {%0,%1,%2,%3};"
        : "+f"(c[0]), "+f"(c[1]), "+f"(c[2]), "+f"(c[3])
        : "r"(a[0]), "r"(a[1]), "r"(a[2]), "r"(a[3]), "r"(b0), "r"(b1));
}

__device__ __forceinline__ float ex2(float x) {
    float r;
    asm("ex2.approx.f32 %0, %1;" : "=f"(r) : "f"(x));
    return r;
}

// ---------------------------------------------------------------------------
// Kernel 0 (fused prep): both weight transposes + LayerNorm in ONE launch.
// blocks [0, 1728)            : transpose W_qkv tile
// blocks [1728, 2304)         : transpose W_out tile
// blocks [2304, 2304 + 8192)  : LayerNorm row (b - 2304)
// ---------------------------------------------------------------------------
#define TQ_BLKS (QKV_N / 32 * (DIM / 32))   // 1728
#define TO_BLKS (DIM / 32 * (DIM / 32))     // 576
#define PREP_BLKS (TQ_BLKS + TO_BLKS + ROWS)

__global__ __launch_bounds__(256) void prep_kernel(
    const float* __restrict__ Wq, __half* __restrict__ WqT,
    const float* __restrict__ Wo, __half* __restrict__ WoT,
    const float* __restrict__ x, const float* __restrict__ g,
    const float* __restrict__ b, __half* __restrict__ xn)
{
    __shared__ float t[32][33];   // also reused as LN scratch (first words)
    const int blk = blockIdx.x;
    const int tid = threadIdx.x;

    if (blk < TQ_BLKS + TO_BLKS) {
        // ---- transpose W[K,N] -> Wt[N,K] (fp16) ----
        const int which = (blk >= TQ_BLKS);
        const int id    = which ? blk - TQ_BLKS : blk;
        const int Ccols = which ? DIM : QKV_N;
        const int nbx   = Ccols / 32;
        const float* W  = which ? Wo  : Wq;
        __half* Wt      = which ? WoT : WqT;
        const int c0 = (id % nbx) * 32, r0 = (id / nbx) * 32;

        const int xq = tid & 31, yq = tid >> 5;
        #pragma unroll
        for (int i = 0; i < 32; i += 8)
            t[yq + i][xq] = W[(size_t)(r0 + yq + i) * Ccols + c0 + xq];
        __syncthreads();
        #pragma unroll
        for (int i = 0; i < 32; i += 8)
            Wt[(size_t)(c0 + yq + i) * DIM + r0 + xq] =
                __float2half_rn(t[xq][yq + i]);
        return;
    }

    // ---- LayerNorm row ----
    const int row = blk - (TQ_BLKS + TO_BLKS);
    const float* xr = x + (size_t)row * DIM;

    float v0 = xr[tid];
    float v1 = xr[tid + 256];
    float v2 = xr[tid + 512];
    float s  = v0 + v1 + v2;
    float ss = v0 * v0 + v1 * v1 + v2 * v2;

    #pragma unroll
    for (int m = 16; m; m >>= 1) {
        s  += __shfl_xor_sync(0xffffffffu, s, m);
        ss += __shfl_xor_sync(0xffffffffu, ss, m);
    }
    float* shs  = &t[0][0];       // 8 floats
    float* shss = &t[1][0];       // 8 floats
    float* stat = &t[2][0];       // 2 floats
    const int w = tid >> 5, l = tid & 31;
    if (l == 0) { shs[w] = s; shss[w] = ss; }
    __syncthreads();
    if (tid == 0) {
        float S = 0.f, SS = 0.f;
        #pragma unroll
        for (int i = 0; i < 8; i++) { S += shs[i]; SS += shss[i]; }
        float mean = S * (1.f / DIM);
        float var  = SS * (1.f / DIM) - mean * mean;
        stat[0] = mean;
        stat[1] = rsqrtf(var + 1e-5f);
    }
    __syncthreads();
    const float mean = stat[0], rstd = stat[1];
    __half* xo = xn + (size_t)row * DIM;
    xo[tid]       = __float2half_rn((v0 - mean) * rstd * g[tid]       + b[tid]);
    xo[tid + 256] = __float2half_rn((v1 - mean) * rstd * g[tid + 256] + b[tid + 256]);
    xo[tid + 512] = __float2half_rn((v2 - mean) * rstd * g[tid + 512] + b[tid + 512]);
}

// ---------------------------------------------------------------------------
// Kernel 2/4: fp16 mma GEMM (R8 config — fastest measured).
// Block 256x128, 8 warps (4m x 2n), warp tile 64x64, BK=32,
// 3-stage cp.async ring, ONE __syncthreads per K-chunk.
// ---------------------------------------------------------------------------
#define GSTR 40
#define G_AS  (256 * GSTR)
#define G_BS  (128 * GSTR)
#define G_SMEM ((3 * G_AS + 3 * G_BS) * 2)   // 92160 bytes

__global__ __launch_bounds__(256) void gemm_h(
    const __half* __restrict__ A, const __half* __restrict__ Bt,
    const float* __restrict__ bias, void* __restrict__ Cout,
    int N, int K, int half_out)
{
    extern __shared__ __half gsm[];
    __half* As = gsm;
    __half* Bs = gsm + 3 * G_AS;

    const int tid  = threadIdx.x;
    const int lane = tid & 31;
    const int wid  = tid >> 5;
    const int wm = (wid & 3) * 64;
    const int wn = (wid >> 2) * 64;
    const int qr = lane >> 2, qc = lane & 3;
    const int bx = blockIdx.x, by = blockIdx.y;

    const __half* Ab = A  + (size_t)by * 256 * K;
    const __half* Bb = Bt + (size_t)bx * 128 * K;

    const int lr = tid >> 2;
    const int lc = (tid & 3) * 8;

    auto load_stage = [&](int st, int k0) {
        uint32_t au = smem_u32(As + st * G_AS);
        uint32_t bu = smem_u32(Bs + st * G_BS);
        #pragma unroll
        for (int j = 0; j < 4; j++) {
            const int r = lr + j * 64;
            cp16(au + (uint32_t)(r * GSTR + lc) * 2, Ab + (size_t)r * K + k0 + lc);
        }
        #pragma unroll
        for (int j = 0; j < 2; j++) {
            const int r = lr + j * 64;
            cp16(bu + (uint32_t)(r * GSTR + lc) * 2, Bb + (size_t)r * K + k0 + lc);
        }
        CP_COMMIT();
    };

    float acc[4][8][4];
    #pragma unroll
    for (int mi = 0; mi < 4; mi++)
        #pragma unroll
        for (int ni = 0; ni < 8; ni++)
            #pragma unroll
            for (int j = 0; j < 4; j++) acc[mi][ni][j] = 0.f;

    const int NC = K / 32;

    load_stage(0, 0);
    load_stage(1, 32);

    for (int kc = 0; kc < NC; kc++) {
        if (kc + 2 < NC) CP_WAIT1(); else CP_WAIT0();
        __syncthreads();
        if (kc + 2 < NC) load_stage((kc + 2) % 3, (kc + 2) * 32);

        const int st = kc % 3;
        const uint32_t a_base = smem_u32(As + st * G_AS);
        const uint32_t b_base = smem_u32(Bs + st * G_BS);

        #pragma unroll
        for (int ks = 0; ks < 2; ks++) {
            const int k0 = ks * 16;
            uint32_t af[4][4];
            #pragma unroll
            for (int mi = 0; mi < 4; mi++) {
                const uint32_t ad = a_base +
                    (uint32_t)((wm + mi * 16 + (lane & 15)) * GSTR
                               + k0 + ((lane >> 4) << 3)) * 2;
                ldm4(af[mi], ad);
            }
            #pragma unroll
            for (int np = 0; np < 4; np++) {
                uint32_t bf[4];
                const uint32_t bd = b_base +
                    (uint32_t)((wn + np * 16 + (lane & 7) + ((lane >> 4) << 3)) * GSTR
                               + k0 + (((lane >> 3) & 1) << 3)) * 2;
                ldm4(bf, bd);
                #pragma unroll
                for (int mi = 0; mi < 4; mi++) {
                    mma16(acc[mi][2 * np],     af[mi], bf[0], bf[1]);
                    mma16(acc[mi][2 * np + 1], af[mi], bf[2], bf[3]);
                }
            }
        }
    }

    const int cb = bx * 128 + wn;
    if (half_out) {
        __half* C = (__half*)Cout;
        #pragma unroll
        for (int mi = 0; mi < 4; mi++)
            #pragma unroll
            for (int hf = 0; hf < 2; hf++) {
                const int row = by * 256 + wm + mi * 16 + qr + hf * 8;
                __half* Cp = C + (size_t)row * N + cb;
                #pragma unroll
                for (int ni = 0; ni < 8; ni++) {
                    const int c = ni * 8 + 2 * qc;
                    *(__half2*)(Cp + c) = __floats2half2_rn(
                        acc[mi][ni][hf * 2 + 0] + bias[cb + c],
                        acc[mi][ni][hf * 2 + 1] + bias[cb + c + 1]);
                }
            }
    } else {
        float* C = (float*)Cout;
        #pragma unroll
        for (int mi = 0; mi < 4; mi++)
            #pragma unroll
            for (int hf = 0; hf < 2; hf++) {
                const int row = by * 256 + wm + mi * 16 + qr + hf * 8;
                float* Cp = C + (size_t)row * N + cb;
                #pragma unroll
                for (int ni = 0; ni < 8; ni++) {
                    const int c = ni * 8 + 2 * qc;
                    float2 v;
                    v.x = acc[mi][ni][hf * 2 + 0] + bias[cb + c];
                    v.y = acc[mi][ni][hf * 2 + 1] + bias[cb + c + 1];
                    *(float2*)(Cp + c) = v;
                }
            }
    }
}

// ---------------------------------------------------------------------------
// Kernel 3: fp16 flash attention.  BR=64, BC=64, d=64.  4 warps; warp owns
// 16 query rows.  Register-resident P (S C-frag == P A-frag layout).
// Warp-uniform skip of O-rescale when the running max is unchanged.
// 2-stage cp.async K/V.
// ---------------------------------------------------------------------------
#define FSTR 72
#define SC_L2E 0.18033688011112042f          // 0.125 * log2(e)

__global__ __launch_bounds__(128) void flash_h(
    const __half* __restrict__ qkv, __half* __restrict__ out)
{
    extern __shared__ __half fs[];
    __half* Qs = fs;
    __half* Kst[2] = { fs + 1 * 64 * FSTR, fs + 2 * 64 * FSTR };
    __half* Vst[2] = { fs + 3 * 64 * FSTR, fs + 4 * 64 * FSTR };

    const int tid  = threadIdx.x;
    const int lane = tid & 31;
    const int wid  = tid >> 5;
    const int qr = lane >> 2, qc = lane & 3;
    const int m0 = wid * 16;

    const int qt = blockIdx.x;
    const int bh = blockIdx.y;
    const int bb = bh / HEADS, h = bh % HEADS;

    const __half* base = qkv + (size_t)bb * SEQ * QKV_N;
    const __half* qb = base + h * DHEAD;
    const __half* kb = base + INNER + h * DHEAD;
    const __half* vb = base + 2 * INNER + h * DHEAD;

    const uint32_t q_u = smem_u32(Qs);
    const uint32_t k_u[2] = { smem_u32(Kst[0]), smem_u32(Kst[1]) };
    const uint32_t v_u[2] = { smem_u32(Vst[0]), smem_u32(Vst[1]) };

    // prologue: Q tile + K/V stage 0 (one group)
    #pragma unroll
    for (int j = 0; j < 4; j++) {
        const int i = tid + j * 128;
        const int r = i >> 3, cg = (i & 7) * 8;
        cp16(q_u + (uint32_t)(r * FSTR + cg) * 2,
             qb + (size_t)(qt * 64 + r) * QKV_N + cg);
    }
    #pragma unroll
    for (int j = 0; j < 4; j++) {
        const int i = tid + j * 128;
        const int r = i >> 3, cg = (i & 7) * 8;
        const size_t off = (size_t)r * QKV_N + cg;
        cp16(k_u[0] + (uint32_t)(r * FSTR + cg) * 2, kb + off);
        cp16(v_u[0] + (uint32_t)(r * FSTR + cg) * 2, vb + off);
    }
    CP_COMMIT();

    float mrow[2] = {-1e30f, -1e30f};
    float lrow[2] = {0.f, 0.f};
    float o[8][4];
    #pragma unroll
    for (int ni = 0; ni < 8; ni++)
        #pragma unroll
        for (int j = 0; j < 4; j++) o[ni][j] = 0.f;

    uint32_t qf[4][4];
    const int NT = SEQ / 64;

    for (int t = 0; t < NT; t++) {
        const int buf = t & 1;
        if (t + 1 < NT) {
            #pragma unroll
            for (int j = 0; j < 4; j++) {
                const int i = tid + j * 128;
                const int r = i >> 3, cg = (i & 7) * 8;
                const size_t off = (size_t)((t + 1) * 64 + r) * QKV_N + cg;
                cp16(k_u[buf ^ 1] + (uint32_t)(r * FSTR + cg) * 2, kb + off);
                cp16(v_u[buf ^ 1] + (uint32_t)(r * FSTR + cg) * 2, vb + off);
            }
            CP_COMMIT();
            CP_WAIT1();
        } else {
            CP_WAIT0();
        }
        __syncthreads();

        if (t == 0) {
            #pragma unroll
            for (int ks = 0; ks < 4; ks++)
                ldm4(qf[ks], q_u + (uint32_t)((m0 + (lane & 15)) * FSTR
                         + ks * 16 + ((lane >> 4) << 3)) * 2);
        }

        // ---- S = Q @ K^T ----
        float s[8][4];
        #pragma unroll
        for (int ni = 0; ni < 8; ni++)
            #pragma unroll
            for (int j = 0; j < 4; j++) s[ni][j] = 0.f;

        #pragma unroll
        for (int ks = 0; ks < 4; ks++) {
            const int k0 = ks * 16;
            #pragma unroll
            for (int np = 0; np < 4; np++) {
                uint32_t bf[4];
                const uint32_t bd = k_u[buf] +
                    (uint32_t)((np * 16 + (lane & 7) + ((lane >> 4) << 3)) * FSTR
                               + k0 + (((lane >> 3) & 1) << 3)) * 2;
                ldm4(bf, bd);
                mma16(s[2 * np],     qf[ks], bf[0], bf[1]);
                mma16(s[2 * np + 1], qf[ks], bf[2], bf[3]);
            }
        }

        // ---- online softmax in exp2 domain ----
        #pragma unroll
        for (int ni = 0; ni < 8; ni++)
            #pragma unroll
            for (int j = 0; j < 4; j++) s[ni][j] *= SC_L2E;

        float mx0 = -1e30f, mx1 = -1e30f;
        #pragma unroll
        for (int ni = 0; ni < 8; ni++) {
            mx0 = fmaxf(mx0, fmaxf(s[ni][0], s[ni][1]));
            mx1 = fmaxf(mx1, fmaxf(s[ni][2], s[ni][3]));
        }
        mx0 = fmaxf(mx0, __shfl_xor_sync(0xffffffffu, mx0, 1));
        mx0 = fmaxf(mx0, __shfl_xor_sync(0xffffffffu, mx0, 2));
        mx1 = fmaxf(mx1, __shfl_xor_sync(0xffffffffu, mx1, 1));
        mx1 = fmaxf(mx1, __shfl_xor_sync(0xffffffffu, mx1, 2));

        const float mn0 = fmaxf(mrow[0], mx0);
        const float mn1 = fmaxf(mrow[1], mx1);
        const float al0 = ex2(mrow[0] - mn0);
        const float al1 = ex2(mrow[1] - mn1);
        mrow[0] = mn0; mrow[1] = mn1;

        float sum0 = 0.f, sum1 = 0.f;
        #pragma unroll
        for (int ni = 0; ni < 8; ni++) {
            s[ni][0] = ex2(s[ni][0] - mn0); sum0 += s[ni][0];
            s[ni][1] = ex2(s[ni][1] - mn0); sum0 += s[ni][1];
            s[ni][2] = ex2(s[ni][2] - mn1); sum1 += s[ni][2];
            s[ni][3] = ex2(s[ni][3] - mn1); sum1 += s[ni][3];
        }
        sum0 += __shfl_xor_sync(0xffffffffu, sum0, 1);
        sum0 += __shfl_xor_sync(0xffffffffu, sum0, 2);
        sum1 += __shfl_xor_sync(0xffffffffu, sum1, 1);
        sum1 += __shfl_xor_sync(0xffffffffu, sum1, 2);
        lrow[0] = lrow[0] * al0 + sum0;
        lrow[1] = lrow[1] * al1 + sum1;

        // warp-uniform skip: only rescale O when some row's max changed
        // (al==1 multiply is the identity, so skipping is bit-exact)
        if (__any_sync(0xffffffffu, (al0 != 1.f) | (al1 != 1.f))) {
            #pragma unroll
            for (int ni = 0; ni < 8; ni++) {
                o[ni][0] *= al0; o[ni][1] *= al0;
                o[ni][2] *= al1; o[ni][3] *= al1;
            }
        }

        // ---- O += P @ V : P A-fragments packed directly from S C-frags ----
        #pragma unroll
        for (int ks = 0; ks < 4; ks++) {
            uint32_t pf[4];
            asm("cvt.rn.f16x2.f32 %0, %1, %2;" : "=r"(pf[0])
                : "f"(s[2 * ks][1]),     "f"(s[2 * ks][0]));
            asm("cvt.rn.f16x2.f32 %0, %1, %2;" : "=r"(pf[1])
                : "f"(s[2 * ks][3]),     "f"(s[2 * ks][2]));
            asm("cvt.rn.f16x2.f32 %0, %1, %2;" : "=r"(pf[2])
                : "f"(s[2 * ks + 1][1]), "f"(s[2 * ks + 1][0]));
            asm("cvt.rn.f16x2.f32 %0, %1, %2;" : "=r"(pf[3])
                : "f"(s[2 * ks + 1][3]), "f"(s[2 * ks + 1][2]));
            #pragma unroll
            for (int np = 0; np < 4; np++) {
                uint32_t vf[4];
                const uint32_t vd = v_u[buf] +
                    (uint32_t)((ks * 16 + (lane & 7) + (((lane >> 3) & 1) << 3)) * FSTR
                               + np * 16 + ((lane >> 4) << 3)) * 2;
                ldm4t(vf, vd);
                mma16(o[2 * np],     pf, vf[0], vf[1]);
                mma16(o[2 * np + 1], pf, vf[2], vf[3]);
            }
        }
        __syncthreads();   // protect K/V buf against next prefetch overwrite
    }

    // ---- normalize + store (half) into [b, n, h*64 + d] ----
    const float inv0 = 1.f / lrow[0];
    const float inv1 = 1.f / lrow[1];
    const size_t n0 = (size_t)bb * SEQ + qt * 64 + m0 + qr;
    #pragma unroll
    for (int ni = 0; ni < 8; ni++) {
        const int c = h * DHEAD + ni * 8 + 2 * qc;
        *(__half2*)(out + n0 * INNER + c) =
            __floats2half2_rn(o[ni][0] * inv0, o[ni][1] * inv0);
        *(__half2*)(out + (n0 + 8) * INNER + c) =
            __floats2half2_rn(o[ni][2] * inv1, o[ni][3] * inv1);
    }
}

// ---------------------------------------------------------------------------
extern "C" void kernel_launch(void* const* d_in, const int* in_sizes, int n_in,
                              void* d_out, int out_size)
{
    const float* x     = (const float*)d_in[0];
    const float* ln_g  = (const float*)d_in[1];
    const float* ln_b  = (const float*)d_in[2];
    const float* W_qkv = (const float*)d_in[3];
    const float* b_qkv = (const float*)d_in[4];
    const float* W_out = (const float*)d_in[5];
    const float* b_out = (const float*)d_in[6];
    float* out = (float*)d_out;

    __half *xn, *qkv, *attn, *wtq, *wto;
    cudaGetSymbolAddress((void**)&xn,   g_xn);
    cudaGetSymbolAddress((void**)&qkv,  g_qkv);
    cudaGetSymbolAddress((void**)&attn, g_attn);
    cudaGetSymbolAddress((void**)&wtq,  g_wtq);
    cudaGetSymbolAddress((void**)&wto,  g_wto);

    const int flash_smem = 5 * 64 * FSTR * (int)sizeof(__half);  // 46080
    cudaFuncSetAttribute(gemm_h, cudaFuncAttributeMaxDynamicSharedMemorySize,
                         G_SMEM);
    cudaFuncSetAttribute(flash_h, cudaFuncAttributeMaxDynamicSharedMemorySize,
                         flash_smem);

    // 0) fused prep: both weight transposes + LayerNorm, one launch
    prep_kernel<<<PREP_BLKS, 256>>>(W_qkv, wtq, W_out, wto,
                                    x, ln_g, ln_b, xn);

    // 1) QKV projection (fp16 mma, half out)
    gemm_h<<<dim3(QKV_N / 128, ROWS / 256), 256, G_SMEM>>>(
        xn, wtq, b_qkv, qkv, QKV_N, DIM, 1);

    // 2) attention (fp16 flash, register-resident P, half out)
    flash_h<<<dim3(SEQ / 64, BATCH * HEADS), 128, flash_smem>>>(qkv, attn);

    // 3) output projection (fp16 mma, fp32 out)
    gemm_h<<<dim3(DIM / 128, ROWS / 256), 256, G_SMEM>>>(
        attn, wto, b_out, out, DIM, INNER, 0);
}

// round 13
// speedup vs baseline: 1.2073x; 1.0323x over previous
#include <cuda_runtime.h>
#include <cuda_fp16.h>
#include <cstdint>
#include <math.h>

// Problem constants
#define BATCH 4
#define SEQ   2048
#define DIM   768
#define HEADS 12
#define DHEAD 64
#define INNER 768
#define ROWS  (BATCH * SEQ)        // 8192
#define QKV_N (3 * INNER)          // 2304

// Scratch (allocation-free: __device__ globals) — all intermediates fp16
__device__ __align__(256) __half g_xn[ROWS * DIM];
__device__ __align__(256) __half g_qkv[ROWS * QKV_N];
__device__ __align__(256) __half g_attn[ROWS * INNER];
__device__ __align__(256) __half g_wtq[QKV_N * DIM];   // W_qkv^T [N,K]
__device__ __align__(256) __half g_wto[DIM * INNER];   // W_out^T [N,K]

// ---------------------------------------------------------------------------
// helpers (plain sm_80-era PTX — compiles for bare compute_103)
// ---------------------------------------------------------------------------
__device__ __forceinline__ uint32_t smem_u32(const void* p) {
    uint32_t a;
    asm("{ .reg .u64 t; cvta.to.shared.u64 t, %1; cvt.u32.u64 %0, t; }"
        : "=r"(a) : "l"(p));
    return a;
}

__device__ __forceinline__ void cp16(uint32_t dst, const void* src) {
    asm volatile("cp.async.cg.shared.global [%0], [%1], 16;"
                 :: "r"(dst), "l"(src));
}
#define CP_COMMIT() asm volatile("cp.async.commit_group;")
#define CP_WAIT0()  asm volatile("cp.async.wait_group 0;")
#define CP_WAIT1()  asm volatile("cp.async.wait_group 1;")

__device__ __forceinline__ void ldm4(uint32_t r[4], uint32_t a) {
    asm volatile("ldmatrix.sync.aligned.m8n8.x4.shared.b16 {%0,%1,%2,%3}, [%4];"
        : "=r"(r[0]), "=r"(r[1]), "=r"(r[2]), "=r"(r[3]) : "r"(a));
}
__device__ __forceinline__ void ldm4t(uint32_t r[4], uint32_t a) {
    asm volatile("ldmatrix.sync.aligned.m8n8.x4.trans.shared.b16 {%0,%1,%2,%3}, [%4];"
        : "=r"(r[0]), "=r"(r[1]), "=r"(r[2]), "=r"(r[3]) : "r"(a));
}

__device__ __forceinline__ void mma16(float c[4], const uint32_t a[4],
                                      uint32_t b0, uint32_t b1) {
    asm volatile(
        "mma.sync.aligned.m16n8k16.row.col.f32.f16.f16.f32 "
        "{%0,%1,%2,%3}, {%4,%5,%6,%7}, {%8,%9}, {%0,%1,%2,%3};"
        : "+f"(c[0]), "+f"(c[1]), "+f"(c[2]), "+f"(c[3])
        : "r"(a[0]), "r"(a[1]), "r"(a[2]), "r"(a[3]), "r"(b0), "r"(b1));
}

__device__ __forceinline__ float ex2(float x) {
    float r;
    asm("ex2.approx.f32 %0, %1;" : "=f"(r) : "f"(x));
    return r;
}

// ---------------------------------------------------------------------------
// Kernel 0 (fused prep): both weight transposes + LayerNorm in ONE launch.
// ---------------------------------------------------------------------------
#define TQ_BLKS (QKV_N / 32 * (DIM / 32))   // 1728
#define TO_BLKS (DIM / 32 * (DIM / 32))     // 576
#define PREP_BLKS (TQ_BLKS + TO_BLKS + ROWS)

__global__ __launch_bounds__(256) void prep_kernel(
    const float* __restrict__ Wq, __half* __restrict__ WqT,
    const float* __restrict__ Wo, __half* __restrict__ WoT,
    const float* __restrict__ x, const float* __restrict__ g,
    const float* __restrict__ b, __half* __restrict__ xn)
{
    __shared__ float t[32][33];
    const int blk = blockIdx.x;
    const int tid = threadIdx.x;

    if (blk < TQ_BLKS + TO_BLKS) {
        const int which = (blk >= TQ_BLKS);
        const int id    = which ? blk - TQ_BLKS : blk;
        const int Ccols = which ? DIM : QKV_N;
        const int nbx   = Ccols / 32;
        const float* W  = which ? Wo  : Wq;
        __half* Wt      = which ? WoT : WqT;
        const int c0 = (id % nbx) * 32, r0 = (id / nbx) * 32;

        const int xq = tid & 31, yq = tid >> 5;
        #pragma unroll
        for (int i = 0; i < 32; i += 8)
            t[yq + i][xq] = W[(size_t)(r0 + yq + i) * Ccols + c0 + xq];
        __syncthreads();
        #pragma unroll
        for (int i = 0; i < 32; i += 8)
            Wt[(size_t)(c0 + yq + i) * DIM + r0 + xq] =
                __float2half_rn(t[xq][yq + i]);
        return;
    }

    const int row = blk - (TQ_BLKS + TO_BLKS);
    const float* xr = x + (size_t)row * DIM;

    float v0 = xr[tid];
    float v1 = xr[tid + 256];
    float v2 = xr[tid + 512];
    float s  = v0 + v1 + v2;
    float ss = v0 * v0 + v1 * v1 + v2 * v2;

    #pragma unroll
    for (int m = 16; m; m >>= 1) {
        s  += __shfl_xor_sync(0xffffffffu, s, m);
        ss += __shfl_xor_sync(0xffffffffu, ss, m);
    }
    float* shs  = &t[0][0];
    float* shss = &t[1][0];
    float* stat = &t[2][0];
    const int w = tid >> 5, l = tid & 31;
    if (l == 0) { shs[w] = s; shss[w] = ss; }
    __syncthreads();
    if (tid == 0) {
        float S = 0.f, SS = 0.f;
        #pragma unroll
        for (int i = 0; i < 8; i++) { S += shs[i]; SS += shss[i]; }
        float mean = S * (1.f / DIM);
        float var  = SS * (1.f / DIM) - mean * mean;
        stat[0] = mean;
        stat[1] = rsqrtf(var + 1e-5f);
    }
    __syncthreads();
    const float mean = stat[0], rstd = stat[1];
    __half* xo = xn + (size_t)row * DIM;
    xo[tid]       = __float2half_rn((v0 - mean) * rstd * g[tid]       + b[tid]);
    xo[tid + 256] = __float2half_rn((v1 - mean) * rstd * g[tid + 256] + b[tid + 256]);
    xo[tid + 512] = __float2half_rn((v2 - mean) * rstd * g[tid + 512] + b[tid + 512]);
}

// ---------------------------------------------------------------------------
// Kernel 2: fp16 mma GEMM for QKV (R8 config).
// Block 256x128, 8 warps (4m x 2n), warp tile 64x64, BK=32,
// 3-stage cp.async ring, ONE __syncthreads per K-chunk.  half output.
// ---------------------------------------------------------------------------
#define GSTR 40
#define G_AS  (256 * GSTR)
#define G_BS  (128 * GSTR)
#define G_SMEM ((3 * G_AS + 3 * G_BS) * 2)   // 92160 bytes

__global__ __launch_bounds__(256) void gemm_h(
    const __half* __restrict__ A, const __half* __restrict__ Bt,
    const float* __restrict__ bias, __half* __restrict__ C, int N, int K)
{
    extern __shared__ __half gsm[];
    __half* As = gsm;
    __half* Bs = gsm + 3 * G_AS;

    const int tid  = threadIdx.x;
    const int lane = tid & 31;
    const int wid  = tid >> 5;
    const int wm = (wid & 3) * 64;
    const int wn = (wid >> 2) * 64;
    const int qr = lane >> 2, qc = lane & 3;
    const int bx = blockIdx.x, by = blockIdx.y;

    const __half* Ab = A  + (size_t)by * 256 * K;
    const __half* Bb = Bt + (size_t)bx * 128 * K;

    const int lr = tid >> 2;
    const int lc = (tid & 3) * 8;

    auto load_stage = [&](int st, int k0) {
        uint32_t au = smem_u32(As + st * G_AS);
        uint32_t bu = smem_u32(Bs + st * G_BS);
        #pragma unroll
        for (int j = 0; j < 4; j++) {
            const int r = lr + j * 64;
            cp16(au + (uint32_t)(r * GSTR + lc) * 2, Ab + (size_t)r * K + k0 + lc);
        }
        #pragma unroll
        for (int j = 0; j < 2; j++) {
            const int r = lr + j * 64;
            cp16(bu + (uint32_t)(r * GSTR + lc) * 2, Bb + (size_t)r * K + k0 + lc);
        }
        CP_COMMIT();
    };

    float acc[4][8][4];
    #pragma unroll
    for (int mi = 0; mi < 4; mi++)
        #pragma unroll
        for (int ni = 0; ni < 8; ni++)
            #pragma unroll
            for (int j = 0; j < 4; j++) acc[mi][ni][j] = 0.f;

    const int NC = K / 32;

    load_stage(0, 0);
    load_stage(1, 32);

    for (int kc = 0; kc < NC; kc++) {
        if (kc + 2 < NC) CP_WAIT1(); else CP_WAIT0();
        __syncthreads();
        if (kc + 2 < NC) load_stage((kc + 2) % 3, (kc + 2) * 32);

        const int st = kc % 3;
        const uint32_t a_base = smem_u32(As + st * G_AS);
        const uint32_t b_base = smem_u32(Bs + st * G_BS);

        #pragma unroll
        for (int ks = 0; ks < 2; ks++) {
            const int k0 = ks * 16;
            uint32_t af[4][4];
            #pragma unroll
            for (int mi = 0; mi < 4; mi++) {
                const uint32_t ad = a_base +
                    (uint32_t)((wm + mi * 16 + (lane & 15)) * GSTR
                               + k0 + ((lane >> 4) << 3)) * 2;
                ldm4(af[mi], ad);
            }
            #pragma unroll
            for (int np = 0; np < 4; np++) {
                uint32_t bf[4];
                const uint32_t bd = b_base +
                    (uint32_t)((wn + np * 16 + (lane & 7) + ((lane >> 4) << 3)) * GSTR
                               + k0 + (((lane >> 3) & 1) << 3)) * 2;
                ldm4(bf, bd);
                #pragma unroll
                for (int mi = 0; mi < 4; mi++) {
                    mma16(acc[mi][2 * np],     af[mi], bf[0], bf[1]);
                    mma16(acc[mi][2 * np + 1], af[mi], bf[2], bf[3]);
                }
            }
        }
    }

    const int cb = bx * 128 + wn;
    #pragma unroll
    for (int mi = 0; mi < 4; mi++)
        #pragma unroll
        for (int hf = 0; hf < 2; hf++) {
            const int row = by * 256 + wm + mi * 16 + qr + hf * 8;
            __half* Cp = C + (size_t)row * N + cb;
            #pragma unroll
            for (int ni = 0; ni < 8; ni++) {
                const int c = ni * 8 + 2 * qc;
                *(__half2*)(Cp + c) = __floats2half2_rn(
                    acc[mi][ni][hf * 2 + 0] + bias[cb + c],
                    acc[mi][ni][hf * 2 + 1] + bias[cb + c + 1]);
            }
        }
}

// ---------------------------------------------------------------------------
// Kernel 4: fp16 mma GEMM for out-projection (R7 config, 2 CTA/SM).
// Block 128x128, 8 warps (4m x 2n), warp tile 32x64, BK=32, 2-stage.
// 384 CTAs at 2 CTA/SM balances far better than 192 CTAs at 1 CTA/SM.
// fp32 output.
// ---------------------------------------------------------------------------
__global__ __launch_bounds__(256) void gemm_o(
    const __half* __restrict__ A, const __half* __restrict__ Bt,
    const float* __restrict__ bias, float* __restrict__ C, int N, int K)
{
    __shared__ __half As[2][128 * GSTR];
    __shared__ __half Bs[2][128 * GSTR];

    const int tid  = threadIdx.x;
    const int lane = tid & 31;
    const int wid  = tid >> 5;
    const int wm = (wid >> 1) * 32;
    const int wn = (wid & 1) * 64;
    const int qr = lane >> 2, qc = lane & 3;
    const int bx = blockIdx.x, by = blockIdx.y;

    const __half* Ab = A  + (size_t)by * 128 * K;
    const __half* Bb = Bt + (size_t)bx * 128 * K;

    const int lr = tid >> 2;
    const int lc = (tid & 3) * 8;
    const int lr2 = (tid + 256) >> 2;

    {
        uint32_t au = smem_u32(As[0]);
        uint32_t bu = smem_u32(Bs[0]);
        cp16(au + (uint32_t)(lr  * GSTR + lc) * 2, Ab + (size_t)lr  * K + lc);
        cp16(bu + (uint32_t)(lr  * GSTR + lc) * 2, Bb + (size_t)lr  * K + lc);
        cp16(au + (uint32_t)(lr2 * GSTR + lc) * 2, Ab + (size_t)lr2 * K + lc);
        cp16(bu + (uint32_t)(lr2 * GSTR + lc) * 2, Bb + (size_t)lr2 * K + lc);
        CP_COMMIT();
    }

    float acc[2][8][4];
    #pragma unroll
    for (int mi = 0; mi < 2; mi++)
        #pragma unroll
        for (int ni = 0; ni < 8; ni++)
            #pragma unroll
            for (int j = 0; j < 4; j++) acc[mi][ni][j] = 0.f;

    const int NC = K / 32;
    for (int kc = 0; kc < NC; kc++) {
        const int buf = kc & 1;
        if (kc + 1 < NC) {
            const int k8 = (kc + 1) * 32;
            uint32_t au = smem_u32(As[buf ^ 1]);
            uint32_t bu = smem_u32(Bs[buf ^ 1]);
            cp16(au + (uint32_t)(lr  * GSTR + lc) * 2, Ab + (size_t)lr  * K + k8 + lc);
            cp16(bu + (uint32_t)(lr  * GSTR + lc) * 2, Bb + (size_t)lr  * K + k8 + lc);
            cp16(au + (uint32_t)(lr2 * GSTR + lc) * 2, Ab + (size_t)lr2 * K + k8 + lc);
            cp16(bu + (uint32_t)(lr2 * GSTR + lc) * 2, Bb + (size_t)lr2 * K + k8 + lc);
            CP_COMMIT();
            CP_WAIT1();
        } else {
            CP_WAIT0();
        }
        __syncthreads();

        const uint32_t a_base = smem_u32(As[buf]);
        const uint32_t b_base = smem_u32(Bs[buf]);
        #pragma unroll
        for (int ks = 0; ks < 2; ks++) {
            const int k0 = ks * 16;
            uint32_t af[2][4];
            #pragma unroll
            for (int mi = 0; mi < 2; mi++) {
                const uint32_t ad = a_base +
                    (uint32_t)((wm + mi * 16 + (lane & 15)) * GSTR
                               + k0 + ((lane >> 4) << 3)) * 2;
                ldm4(af[mi], ad);
            }
            #pragma unroll
            for (int np = 0; np < 4; np++) {
                uint32_t bf[4];
                const uint32_t bd = b_base +
                    (uint32_t)((wn + np * 16 + (lane & 7) + ((lane >> 4) << 3)) * GSTR
                               + k0 + (((lane >> 3) & 1) << 3)) * 2;
                ldm4(bf, bd);
                mma16(acc[0][2 * np],     af[0], bf[0], bf[1]);
                mma16(acc[0][2 * np + 1], af[0], bf[2], bf[3]);
                mma16(acc[1][2 * np],     af[1], bf[0], bf[1]);
                mma16(acc[1][2 * np + 1], af[1], bf[2], bf[3]);
            }
        }
        __syncthreads();
    }

    const int cb = bx * 128 + wn;
    #pragma unroll
    for (int mi = 0; mi < 2; mi++)
        #pragma unroll
        for (int hf = 0; hf < 2; hf++) {
            const int row = by * 128 + wm + mi * 16 + qr + hf * 8;
            float* Cp = C + (size_t)row * N + cb;
            #pragma unroll
            for (int ni = 0; ni < 8; ni++) {
                const int c = ni * 8 + 2 * qc;
                float2 v;
                v.x = acc[mi][ni][hf * 2 + 0] + bias[cb + c];
                v.y = acc[mi][ni][hf * 2 + 1] + bias[cb + c + 1];
                *(float2*)(Cp + c) = v;
            }
        }
}

// ---------------------------------------------------------------------------
// Kernel 3: fp16 flash attention.  BR=64, BC=64, d=64.  4 warps; warp owns
// 16 query rows.  Register-resident P.  Warp-uniform rescale skip.
// 2-stage cp.async K/V.
// ---------------------------------------------------------------------------
#define FSTR 72
#define SC_L2E 0.18033688011112042f          // 0.125 * log2(e)

__global__ __launch_bounds__(128) void flash_h(
    const __half* __restrict__ qkv, __half* __restrict__ out)
{
    extern __shared__ __half fs[];
    __half* Qs = fs;
    __half* Kst[2] = { fs + 1 * 64 * FSTR, fs + 2 * 64 * FSTR };
    __half* Vst[2] = { fs + 3 * 64 * FSTR, fs + 4 * 64 * FSTR };

    const int tid  = threadIdx.x;
    const int lane = tid & 31;
    const int wid  = tid >> 5;
    const int qr = lane >> 2, qc = lane & 3;
    const int m0 = wid * 16;

    const int qt = blockIdx.x;
    const int bh = blockIdx.y;
    const int bb = bh / HEADS, h = bh % HEADS;

    const __half* base = qkv + (size_t)bb * SEQ * QKV_N;
    const __half* qb = base + h * DHEAD;
    const __half* kb = base + INNER + h * DHEAD;
    const __half* vb = base + 2 * INNER + h * DHEAD;

    const uint32_t q_u = smem_u32(Qs);
    const uint32_t k_u[2] = { smem_u32(Kst[0]), smem_u32(Kst[1]) };
    const uint32_t v_u[2] = { smem_u32(Vst[0]), smem_u32(Vst[1]) };

    #pragma unroll
    for (int j = 0; j < 4; j++) {
        const int i = tid + j * 128;
        const int r = i >> 3, cg = (i & 7) * 8;
        cp16(q_u + (uint32_t)(r * FSTR + cg) * 2,
             qb + (size_t)(qt * 64 + r) * QKV_N + cg);
    }
    #pragma unroll
    for (int j = 0; j < 4; j++) {
        const int i = tid + j * 128;
        const int r = i >> 3, cg = (i & 7) * 8;
        const size_t off = (size_t)r * QKV_N + cg;
        cp16(k_u[0] + (uint32_t)(r * FSTR + cg) * 2, kb + off);
        cp16(v_u[0] + (uint32_t)(r * FSTR + cg) * 2, vb + off);
    }
    CP_COMMIT();

    float mrow[2] = {-1e30f, -1e30f};
    float lrow[2] = {0.f, 0.f};
    float o[8][4];
    #pragma unroll
    for (int ni = 0; ni < 8; ni++)
        #pragma unroll
        for (int j = 0; j < 4; j++) o[ni][j] = 0.f;

    uint32_t qf[4][4];
    const int NT = SEQ / 64;

    for (int t = 0; t < NT; t++) {
        const int buf = t & 1;
        if (t + 1 < NT) {
            #pragma unroll
            for (int j = 0; j < 4; j++) {
                const int i = tid + j * 128;
                const int r = i >> 3, cg = (i & 7) * 8;
                const size_t off = (size_t)((t + 1) * 64 + r) * QKV_N + cg;
                cp16(k_u[buf ^ 1] + (uint32_t)(r * FSTR + cg) * 2, kb + off);
                cp16(v_u[buf ^ 1] + (uint32_t)(r * FSTR + cg) * 2, vb + off);
            }
            CP_COMMIT();
            CP_WAIT1();
        } else {
            CP_WAIT0();
        }
        __syncthreads();

        if (t == 0) {
            #pragma unroll
            for (int ks = 0; ks < 4; ks++)
                ldm4(qf[ks], q_u + (uint32_t)((m0 + (lane & 15)) * FSTR
                         + ks * 16 + ((lane >> 4) << 3)) * 2);
        }

        // ---- S = Q @ K^T ----
        float s[8][4];
        #pragma unroll
        for (int ni = 0; ni < 8; ni++)
            #pragma unroll
            for (int j = 0; j < 4; j++) s[ni][j] = 0.f;

        #pragma unroll
        for (int ks = 0; ks < 4; ks++) {
            const int k0 = ks * 16;
            #pragma unroll
            for (int np = 0; np < 4; np++) {
                uint32_t bf[4];
                const uint32_t bd = k_u[buf] +
                    (uint32_t)((np * 16 + (lane & 7) + ((lane >> 4) << 3)) * FSTR
                               + k0 + (((lane >> 3) & 1) << 3)) * 2;
                ldm4(bf, bd);
                mma16(s[2 * np],     qf[ks], bf[0], bf[1]);
                mma16(s[2 * np + 1], qf[ks], bf[2], bf[3]);
            }
        }

        // ---- online softmax in exp2 domain ----
        #pragma unroll
        for (int ni = 0; ni < 8; ni++)
            #pragma unroll
            for (int j = 0; j < 4; j++) s[ni][j] *= SC_L2E;

        float mx0 = -1e30f, mx1 = -1e30f;
        #pragma unroll
        for (int ni = 0; ni < 8; ni++) {
            mx0 = fmaxf(mx0, fmaxf(s[ni][0], s[ni][1]));
            mx1 = fmaxf(mx1, fmaxf(s[ni][2], s[ni][3]));
        }
        mx0 = fmaxf(mx0, __shfl_xor_sync(0xffffffffu, mx0, 1));
        mx0 = fmaxf(mx0, __shfl_xor_sync(0xffffffffu, mx0, 2));
        mx1 = fmaxf(mx1, __shfl_xor_sync(0xffffffffu, mx1, 1));
        mx1 = fmaxf(mx1, __shfl_xor_sync(0xffffffffu, mx1, 2));

        const float mn0 = fmaxf(mrow[0], mx0);
        const float mn1 = fmaxf(mrow[1], mx1);
        const float al0 = ex2(mrow[0] - mn0);
        const float al1 = ex2(mrow[1] - mn1);
        mrow[0] = mn0; mrow[1] = mn1;

        float sum0 = 0.f, sum1 = 0.f;
        #pragma unroll
        for (int ni = 0; ni < 8; ni++) {
            s[ni][0] = ex2(s[ni][0] - mn0); sum0 += s[ni][0];
            s[ni][1] = ex2(s[ni][1] - mn0); sum0 += s[ni][1];
            s[ni][2] = ex2(s[ni][2] - mn1); sum1 += s[ni][2];
            s[ni][3] = ex2(s[ni][3] - mn1); sum1 += s[ni][3];
        }
        sum0 += __shfl_xor_sync(0xffffffffu, sum0, 1);
        sum0 += __shfl_xor_sync(0xffffffffu, sum0, 2);
        sum1 += __shfl_xor_sync(0xffffffffu, sum1, 1);
        sum1 += __shfl_xor_sync(0xffffffffu, sum1, 2);
        lrow[0] = lrow[0] * al0 + sum0;
        lrow[1] = lrow[1] * al1 + sum1;

        if (__any_sync(0xffffffffu, (al0 != 1.f) | (al1 != 1.f))) {
            #pragma unroll
            for (int ni = 0; ni < 8; ni++) {
                o[ni][0] *= al0; o[ni][1] *= al0;
                o[ni][2] *= al1; o[ni][3] *= al1;
            }
        }

        // ---- O += P @ V : P A-fragments packed directly from S C-frags ----
        #pragma unroll
        for (int ks = 0; ks < 4; ks++) {
            uint32_t pf[4];
            asm("cvt.rn.f16x2.f32 %0, %1, %2;" : "=r"(pf[0])
                : "f"(s[2 * ks][1]),     "f"(s[2 * ks][0]));
            asm("cvt.rn.f16x2.f32 %0, %1, %2;" : "=r"(pf[1])
                : "f"(s[2 * ks][3]),     "f"(s[2 * ks][2]));
            asm("cvt.rn.f16x2.f32 %0, %1, %2;" : "=r"(pf[2])
                : "f"(s[2 * ks + 1][1]), "f"(s[2 * ks + 1][0]));
            asm("cvt.rn.f16x2.f32 %0, %1, %2;" : "=r"(pf[3])
                : "f"(s[2 * ks + 1][3]), "f"(s[2 * ks + 1][2]));
            #pragma unroll
            for (int np = 0; np < 4; np++) {
                uint32_t vf[4];
                const uint32_t vd = v_u[buf] +
                    (uint32_t)((ks * 16 + (lane & 7) + (((lane >> 3) & 1) << 3)) * FSTR
                               + np * 16 + ((lane >> 4) << 3)) * 2;
                ldm4t(vf, vd);
                mma16(o[2 * np],     pf, vf[0], vf[1]);
                mma16(o[2 * np + 1], pf, vf[2], vf[3]);
            }
        }
        __syncthreads();
    }

    const float inv0 = 1.f / lrow[0];
    const float inv1 = 1.f / lrow[1];
    const size_t n0 = (size_t)bb * SEQ + qt * 64 + m0 + qr;
    #pragma unroll
    for (int ni = 0; ni < 8; ni++) {
        const int c = h * DHEAD + ni * 8 + 2 * qc;
        *(__half2*)(out + n0 * INNER + c) =
            __floats2half2_rn(o[ni][0] * inv0, o[ni][1] * inv0);
        *(__half2*)(out + (n0 + 8) * INNER + c) =
            __floats2half2_rn(o[ni][2] * inv1, o[ni][3] * inv1);
    }
}

// ---------------------------------------------------------------------------
extern "C" void kernel_launch(void* const* d_in, const int* in_sizes, int n_in,
                              void* d_out, int out_size)
{
    const float* x     = (const float*)d_in[0];
    const float* ln_g  = (const float*)d_in[1];
    const float* ln_b  = (const float*)d_in[2];
    const float* W_qkv = (const float*)d_in[3];
    const float* b_qkv = (const float*)d_in[4];
    const float* W_out = (const float*)d_in[5];
    const float* b_out = (const float*)d_in[6];
    float* out = (float*)d_out;

    __half *xn, *qkv, *attn, *wtq, *wto;
    cudaGetSymbolAddress((void**)&xn,   g_xn);
    cudaGetSymbolAddress((void**)&qkv,  g_qkv);
    cudaGetSymbolAddress((void**)&attn, g_attn);
    cudaGetSymbolAddress((void**)&wtq,  g_wtq);
    cudaGetSymbolAddress((void**)&wto,  g_wto);

    const int flash_smem = 5 * 64 * FSTR * (int)sizeof(__half);  // 46080
    cudaFuncSetAttribute(gemm_h, cudaFuncAttributeMaxDynamicSharedMemorySize,
                         G_SMEM);
    cudaFuncSetAttribute(flash_h, cudaFuncAttributeMaxDynamicSharedMemorySize,
                         flash_smem);

    // 0) fused prep: both weight transposes + LayerNorm, one launch
    prep_kernel<<<PREP_BLKS, 256>>>(W_qkv, wtq, W_out, wto,
                                    x, ln_g, ln_b, xn);

    // 1) QKV projection (fp16 mma, 256x128 tiles, half out)
    gemm_h<<<dim3(QKV_N / 128, ROWS / 256), 256, G_SMEM>>>(
        xn, wtq, b_qkv, qkv, QKV_N, DIM);

    // 2) attention (fp16 flash, register-resident P, half out)
    flash_h<<<dim3(SEQ / 64, BATCH * HEADS), 128, flash_smem>>>(qkv, attn);

    // 3) output projection (fp16 mma, 128x128 tiles for wave balance, fp32)
    gemm_o<<<dim3(DIM / 128, ROWS / 128), 256>>>(
        attn, wto, b_out, out, DIM, INNER);
}

// round 14
// speedup vs baseline: 1.2870x; 1.0660x over previous
#include <cuda_runtime.h>
#include <cuda_fp16.h>
#include <cstdint>
#include <math.h>

// Problem constants
#define BATCH 4
#define SEQ   2048
#define DIM   768
#define HEADS 12
#define DHEAD 64
#define INNER 768
#define ROWS  (BATCH * SEQ)        // 8192
#define QKV_N (3 * INNER)          // 2304

// Scratch (allocation-free: __device__ globals) — all intermediates fp16
__device__ __align__(256) __half g_xn[ROWS * DIM];
__device__ __align__(256) __half g_qkv[ROWS * QKV_N];
__device__ __align__(256) __half g_attn[ROWS * INNER];
__device__ __align__(256) __half g_wtq[QKV_N * DIM];   // W_qkv^T [N,K]
__device__ __align__(256) __half g_wto[DIM * INNER];   // W_out^T [N,K]

// ---------------------------------------------------------------------------
// helpers (plain sm_80-era PTX — compiles for bare compute_103)
// ---------------------------------------------------------------------------
__device__ __forceinline__ uint32_t smem_u32(const void* p) {
    uint32_t a;
    asm("{ .reg .u64 t; cvta.to.shared.u64 t, %1; cvt.u32.u64 %0, t; }"
        : "=r"(a) : "l"(p));
    return a;
}

__device__ __forceinline__ void cp16(uint32_t dst, const void* src) {
    asm volatile("cp.async.cg.shared.global [%0], [%1], 16;"
                 :: "r"(dst), "l"(src));
}
#define CP_COMMIT() asm volatile("cp.async.commit_group;")
#define CP_WAIT0()  asm volatile("cp.async.wait_group 0;")
#define CP_WAIT1()  asm volatile("cp.async.wait_group 1;")

__device__ __forceinline__ void ldm4(uint32_t r[4], uint32_t a) {
    asm volatile("ldmatrix.sync.aligned.m8n8.x4.shared.b16 {%0,%1,%2,%3}, [%4];"
        : "=r"(r[0]), "=r"(r[1]), "=r"(r[2]), "=r"(r[3]) : "r"(a));
}
__device__ __forceinline__ void ldm4t(uint32_t r[4], uint32_t a) {
    asm volatile("ldmatrix.sync.aligned.m8n8.x4.trans.shared.b16 {%0,%1,%2,%3}, [%4];"
        : "=r"(r[0]), "=r"(r[1]), "=r"(r[2]), "=r"(r[3]) : "r"(a));
}

__device__ __forceinline__ void mma16(float c[4], const uint32_t a[4],
                                      uint32_t b0, uint32_t b1) {
    asm volatile(
        "mma.sync.aligned.m16n8k16.row.col.f32.f16.f16.f32 "
        "{%0,%1,%2,%3}, {%4,%5,%6,%7}, {%8,%9}, {%0,%1,%2,%3};"
        : "+f"(c[0]), "+f"(c[1]), "+f"(c[2]), "+f"(c[3])
        : "r"(a[0]), "r"(a[1]), "r"(a[2]), "r"(a[3]), "r"(b0), "r"(b1));
}

__device__ __forceinline__ float ex2(float x) {
    float r;
    asm("ex2.approx.f32 %0, %1;" : "=f"(r) : "f"(x));
    return r;
}

// ---------------------------------------------------------------------------
// Kernel 0 (fused prep): both weight transposes + LayerNorm in ONE launch.
// ---------------------------------------------------------------------------
#define TQ_BLKS (QKV_N / 32 * (DIM / 32))   // 1728
#define TO_BLKS (DIM / 32 * (DIM / 32))     // 576
#define PREP_BLKS (TQ_BLKS + TO_BLKS + ROWS)

__global__ __launch_bounds__(256) void prep_kernel(
    const float* __restrict__ Wq, __half* __restrict__ WqT,
    const float* __restrict__ Wo, __half* __restrict__ WoT,
    const float* __restrict__ x, const float* __restrict__ g,
    const float* __restrict__ b, __half* __restrict__ xn)
{
    __shared__ float t[32][33];
    const int blk = blockIdx.x;
    const int tid = threadIdx.x;

    if (blk < TQ_BLKS + TO_BLKS) {
        const int which = (blk >= TQ_BLKS);
        const int id    = which ? blk - TQ_BLKS : blk;
        const int Ccols = which ? DIM : QKV_N;
        const int nbx   = Ccols / 32;
        const float* W  = which ? Wo  : Wq;
        __half* Wt      = which ? WoT : WqT;
        const int c0 = (id % nbx) * 32, r0 = (id / nbx) * 32;

        const int xq = tid & 31, yq = tid >> 5;
        #pragma unroll
        for (int i = 0; i < 32; i += 8)
            t[yq + i][xq] = W[(size_t)(r0 + yq + i) * Ccols + c0 + xq];
        __syncthreads();
        #pragma unroll
        for (int i = 0; i < 32; i += 8)
            Wt[(size_t)(c0 + yq + i) * DIM + r0 + xq] =
                __float2half_rn(t[xq][yq + i]);
        return;
    }

    const int row = blk - (TQ_BLKS + TO_BLKS);
    const float* xr = x + (size_t)row * DIM;

    float v0 = xr[tid];
    float v1 = xr[tid + 256];
    float v2 = xr[tid + 512];
    float s  = v0 + v1 + v2;
    float ss = v0 * v0 + v1 * v1 + v2 * v2;

    #pragma unroll
    for (int m = 16; m; m >>= 1) {
        s  += __shfl_xor_sync(0xffffffffu, s, m);
        ss += __shfl_xor_sync(0xffffffffu, ss, m);
    }
    float* shs  = &t[0][0];
    float* shss = &t[1][0];
    float* stat = &t[2][0];
    const int w = tid >> 5, l = tid & 31;
    if (l == 0) { shs[w] = s; shss[w] = ss; }
    __syncthreads();
    if (tid == 0) {
        float S = 0.f, SS = 0.f;
        #pragma unroll
        for (int i = 0; i < 8; i++) { S += shs[i]; SS += shss[i]; }
        float mean = S * (1.f / DIM);
        float var  = SS * (1.f / DIM) - mean * mean;
        stat[0] = mean;
        stat[1] = rsqrtf(var + 1e-5f);
    }
    __syncthreads();
    const float mean = stat[0], rstd = stat[1];
    __half* xo = xn + (size_t)row * DIM;
    xo[tid]       = __float2half_rn((v0 - mean) * rstd * g[tid]       + b[tid]);
    xo[tid + 256] = __float2half_rn((v1 - mean) * rstd * g[tid + 256] + b[tid + 256]);
    xo[tid + 512] = __float2half_rn((v2 - mean) * rstd * g[tid + 512] + b[tid + 512]);
}

// ---------------------------------------------------------------------------
// Kernel 2: fp16 mma GEMM for QKV.  Block 256x128, 8 warps (4m x 2n),
// warp tile 64x64, BK=64 (halved barrier count vs BK=32), 3-stage cp.async
// ring, ONE __syncthreads per 64-deep K-chunk.  Row stride 72 halfs
// (≡8 mod 32, conflict-free — same class as flash's proven FSTR=72).
// half output.
// ---------------------------------------------------------------------------
#define G2STR 72
#define G2_AS  (256 * G2STR)
#define G2_BS  (128 * G2STR)
#define G2_SMEM ((3 * G2_AS + 3 * G2_BS) * 2)   // 165888 bytes

__global__ __launch_bounds__(256) void gemm_h(
    const __half* __restrict__ A, const __half* __restrict__ Bt,
    const float* __restrict__ bias, __half* __restrict__ C, int N, int K)
{
    extern __shared__ __half gsm[];
    __half* As = gsm;
    __half* Bs = gsm + 3 * G2_AS;

    const int tid  = threadIdx.x;
    const int lane = tid & 31;
    const int wid  = tid >> 5;
    const int wm = (wid & 3) * 64;
    const int wn = (wid >> 2) * 64;
    const int qr = lane >> 2, qc = lane & 3;
    const int bx = blockIdx.x, by = blockIdx.y;

    const __half* Ab = A  + (size_t)by * 256 * K;
    const __half* Bb = Bt + (size_t)bx * 128 * K;

    const int lr  = tid >> 3;          // 0..31 loader row base
    const int lc8 = (tid & 7) * 8;     // 0..56 col (halfs)

    auto load_stage = [&](int st, int k0) {
        uint32_t au = smem_u32(As + st * G2_AS);
        uint32_t bu = smem_u32(Bs + st * G2_BS);
        #pragma unroll
        for (int j = 0; j < 8; j++) {   // A: 256 rows x 64 halfs
            const int r = lr + j * 32;
            cp16(au + (uint32_t)(r * G2STR + lc8) * 2,
                 Ab + (size_t)r * K + k0 + lc8);
        }
        #pragma unroll
        for (int j = 0; j < 4; j++) {   // B: 128 rows x 64 halfs
            const int r = lr + j * 32;
            cp16(bu + (uint32_t)(r * G2STR + lc8) * 2,
                 Bb + (size_t)r * K + k0 + lc8);
        }
        CP_COMMIT();
    };

    float acc[4][8][4];
    #pragma unroll
    for (int mi = 0; mi < 4; mi++)
        #pragma unroll
        for (int ni = 0; ni < 8; ni++)
            #pragma unroll
            for (int j = 0; j < 4; j++) acc[mi][ni][j] = 0.f;

    const int NC = K / 64;   // 12

    load_stage(0, 0);
    load_stage(1, 64);

    for (int kc = 0; kc < NC; kc++) {
        if (kc + 2 < NC) CP_WAIT1(); else CP_WAIT0();
        __syncthreads();
        if (kc + 2 < NC) load_stage((kc + 2) % 3, (kc + 2) * 64);

        const int st = kc % 3;
        const uint32_t a_base = smem_u32(As + st * G2_AS);
        const uint32_t b_base = smem_u32(Bs + st * G2_BS);

        #pragma unroll
        for (int ks = 0; ks < 4; ks++) {
            const int k0 = ks * 16;
            uint32_t af[4][4];
            #pragma unroll
            for (int mi = 0; mi < 4; mi++) {
                const uint32_t ad = a_base +
                    (uint32_t)((wm + mi * 16 + (lane & 15)) * G2STR
                               + k0 + ((lane >> 4) << 3)) * 2;
                ldm4(af[mi], ad);
            }
            #pragma unroll
            for (int np = 0; np < 4; np++) {
                uint32_t bf[4];
                const uint32_t bd = b_base +
                    (uint32_t)((wn + np * 16 + (lane & 7) + ((lane >> 4) << 3)) * G2STR
                               + k0 + (((lane >> 3) & 1) << 3)) * 2;
                ldm4(bf, bd);
                #pragma unroll
                for (int mi = 0; mi < 4; mi++) {
                    mma16(acc[mi][2 * np],     af[mi], bf[0], bf[1]);
                    mma16(acc[mi][2 * np + 1], af[mi], bf[2], bf[3]);
                }
            }
        }
    }

    const int cb = bx * 128 + wn;
    #pragma unroll
    for (int mi = 0; mi < 4; mi++)
        #pragma unroll
        for (int hf = 0; hf < 2; hf++) {
            const int row = by * 256 + wm + mi * 16 + qr + hf * 8;
            __half* Cp = C + (size_t)row * N + cb;
            #pragma unroll
            for (int ni = 0; ni < 8; ni++) {
                const int c = ni * 8 + 2 * qc;
                *(__half2*)(Cp + c) = __floats2half2_rn(
                    acc[mi][ni][hf * 2 + 0] + bias[cb + c],
                    acc[mi][ni][hf * 2 + 1] + bias[cb + c + 1]);
            }
        }
}

// ---------------------------------------------------------------------------
// Kernel 4: fp16 mma GEMM for out-projection.  Block 128x128, 8 warps
// (4m x 2n), warp tile 32x64, BK=64, 2-stage (dynamic smem 73.7 KB ->
// still 2 CTAs/SM at 96 regs).  fp32 output.
// ---------------------------------------------------------------------------
#define GO_S   (128 * G2STR)
#define GO_SMEM ((4 * GO_S) * 2)   // 2 stages x (A+B) = 73728 bytes

__global__ __launch_bounds__(256) void gemm_o(
    const __half* __restrict__ A, const __half* __restrict__ Bt,
    const float* __restrict__ bias, float* __restrict__ C, int N, int K)
{
    extern __shared__ __half osm[];
    __half* As = osm;                 // 2 stages of 128 x G2STR
    __half* Bs = osm + 2 * GO_S;      // 2 stages of 128 x G2STR

    const int tid  = threadIdx.x;
    const int lane = tid & 31;
    const int wid  = tid >> 5;
    const int wm = (wid >> 1) * 32;
    const int wn = (wid & 1) * 64;
    const int qr = lane >> 2, qc = lane & 3;
    const int bx = blockIdx.x, by = blockIdx.y;

    const __half* Ab = A  + (size_t)by * 128 * K;
    const __half* Bb = Bt + (size_t)bx * 128 * K;

    const int lr  = tid >> 3;
    const int lc8 = (tid & 7) * 8;

    auto load_stage = [&](int st, int k0) {
        uint32_t au = smem_u32(As + st * GO_S);
        uint32_t bu = smem_u32(Bs + st * GO_S);
        #pragma unroll
        for (int j = 0; j < 4; j++) {
            const int r = lr + j * 32;
            cp16(au + (uint32_t)(r * G2STR + lc8) * 2,
                 Ab + (size_t)r * K + k0 + lc8);
            cp16(bu + (uint32_t)(r * G2STR + lc8) * 2,
                 Bb + (size_t)r * K + k0 + lc8);
        }
        CP_COMMIT();
    };

    load_stage(0, 0);

    float acc[2][8][4];
    #pragma unroll
    for (int mi = 0; mi < 2; mi++)
        #pragma unroll
        for (int ni = 0; ni < 8; ni++)
            #pragma unroll
            for (int j = 0; j < 4; j++) acc[mi][ni][j] = 0.f;

    const int NC = K / 64;   // 12
    for (int kc = 0; kc < NC; kc++) {
        const int buf = kc & 1;
        if (kc + 1 < NC) {
            load_stage(buf ^ 1, (kc + 1) * 64);
            CP_WAIT1();
        } else {
            CP_WAIT0();
        }
        __syncthreads();

        const uint32_t a_base = smem_u32(As + buf * GO_S);
        const uint32_t b_base = smem_u32(Bs + buf * GO_S);
        #pragma unroll
        for (int ks = 0; ks < 4; ks++) {
            const int k0 = ks * 16;
            uint32_t af[2][4];
            #pragma unroll
            for (int mi = 0; mi < 2; mi++) {
                const uint32_t ad = a_base +
                    (uint32_t)((wm + mi * 16 + (lane & 15)) * G2STR
                               + k0 + ((lane >> 4) << 3)) * 2;
                ldm4(af[mi], ad);
            }
            #pragma unroll
            for (int np = 0; np < 4; np++) {
                uint32_t bf[4];
                const uint32_t bd = b_base +
                    (uint32_t)((wn + np * 16 + (lane & 7) + ((lane >> 4) << 3)) * G2STR
                               + k0 + (((lane >> 3) & 1) << 3)) * 2;
                ldm4(bf, bd);
                mma16(acc[0][2 * np],     af[0], bf[0], bf[1]);
                mma16(acc[0][2 * np + 1], af[0], bf[2], bf[3]);
                mma16(acc[1][2 * np],     af[1], bf[0], bf[1]);
                mma16(acc[1][2 * np + 1], af[1], bf[2], bf[3]);
            }
        }
        __syncthreads();
    }

    const int cb = bx * 128 + wn;
    #pragma unroll
    for (int mi = 0; mi < 2; mi++)
        #pragma unroll
        for (int hf = 0; hf < 2; hf++) {
            const int row = by * 128 + wm + mi * 16 + qr + hf * 8;
            float* Cp = C + (size_t)row * N + cb;
            #pragma unroll
            for (int ni = 0; ni < 8; ni++) {
                const int c = ni * 8 + 2 * qc;
                float2 v;
                v.x = acc[mi][ni][hf * 2 + 0] + bias[cb + c];
                v.y = acc[mi][ni][hf * 2 + 1] + bias[cb + c + 1];
                *(float2*)(Cp + c) = v;
            }
        }
}

// ---------------------------------------------------------------------------
// Kernel 3: fp16 flash attention (unchanged from R13 best).
// BR=64, BC=64, d=64.  4 warps; warp owns 16 query rows.  Register-resident
// P.  Warp-uniform rescale skip.  2-stage cp.async K/V.
// ---------------------------------------------------------------------------
#define FSTR 72
#define SC_L2E 0.18033688011112042f          // 0.125 * log2(e)

__global__ __launch_bounds__(128) void flash_h(
    const __half* __restrict__ qkv, __half* __restrict__ out)
{
    extern __shared__ __half fs[];
    __half* Qs = fs;
    __half* Kst[2] = { fs + 1 * 64 * FSTR, fs + 2 * 64 * FSTR };
    __half* Vst[2] = { fs + 3 * 64 * FSTR, fs + 4 * 64 * FSTR };

    const int tid  = threadIdx.x;
    const int lane = tid & 31;
    const int wid  = tid >> 5;
    const int qr = lane >> 2, qc = lane & 3;
    const int m0 = wid * 16;

    const int qt = blockIdx.x;
    const int bh = blockIdx.y;
    const int bb = bh / HEADS, h = bh % HEADS;

    const __half* base = qkv + (size_t)bb * SEQ * QKV_N;
    const __half* qb = base + h * DHEAD;
    const __half* kb = base + INNER + h * DHEAD;
    const __half* vb = base + 2 * INNER + h * DHEAD;

    const uint32_t q_u = smem_u32(Qs);
    const uint32_t k_u[2] = { smem_u32(Kst[0]), smem_u32(Kst[1]) };
    const uint32_t v_u[2] = { smem_u32(Vst[0]), smem_u32(Vst[1]) };

    #pragma unroll
    for (int j = 0; j < 4; j++) {
        const int i = tid + j * 128;
        const int r = i >> 3, cg = (i & 7) * 8;
        cp16(q_u + (uint32_t)(r * FSTR + cg) * 2,
             qb + (size_t)(qt * 64 + r) * QKV_N + cg);
    }
    #pragma unroll
    for (int j = 0; j < 4; j++) {
        const int i = tid + j * 128;
        const int r = i >> 3, cg = (i & 7) * 8;
        const size_t off = (size_t)r * QKV_N + cg;
        cp16(k_u[0] + (uint32_t)(r * FSTR + cg) * 2, kb + off);
        cp16(v_u[0] + (uint32_t)(r * FSTR + cg) * 2, vb + off);
    }
    CP_COMMIT();

    float mrow[2] = {-1e30f, -1e30f};
    float lrow[2] = {0.f, 0.f};
    float o[8][4];
    #pragma unroll
    for (int ni = 0; ni < 8; ni++)
        #pragma unroll
        for (int j = 0; j < 4; j++) o[ni][j] = 0.f;

    uint32_t qf[4][4];
    const int NT = SEQ / 64;

    for (int t = 0; t < NT; t++) {
        const int buf = t & 1;
        if (t + 1 < NT) {
            #pragma unroll
            for (int j = 0; j < 4; j++) {
                const int i = tid + j * 128;
                const int r = i >> 3, cg = (i & 7) * 8;
                const size_t off = (size_t)((t + 1) * 64 + r) * QKV_N + cg;
                cp16(k_u[buf ^ 1] + (uint32_t)(r * FSTR + cg) * 2, kb + off);
                cp16(v_u[buf ^ 1] + (uint32_t)(r * FSTR + cg) * 2, vb + off);
            }
            CP_COMMIT();
            CP_WAIT1();
        } else {
            CP_WAIT0();
        }
        __syncthreads();

        if (t == 0) {
            #pragma unroll
            for (int ks = 0; ks < 4; ks++)
                ldm4(qf[ks], q_u + (uint32_t)((m0 + (lane & 15)) * FSTR
                         + ks * 16 + ((lane >> 4) << 3)) * 2);
        }

        // ---- S = Q @ K^T ----
        float s[8][4];
        #pragma unroll
        for (int ni = 0; ni < 8; ni++)
            #pragma unroll
            for (int j = 0; j < 4; j++) s[ni][j] = 0.f;

        #pragma unroll
        for (int ks = 0; ks < 4; ks++) {
            const int k0 = ks * 16;
            #pragma unroll
            for (int np = 0; np < 4; np++) {
                uint32_t bf[4];
                const uint32_t bd = k_u[buf] +
                    (uint32_t)((np * 16 + (lane & 7) + ((lane >> 4) << 3)) * FSTR
                               + k0 + (((lane >> 3) & 1) << 3)) * 2;
                ldm4(bf, bd);
                mma16(s[2 * np],     qf[ks], bf[0], bf[1]);
                mma16(s[2 * np + 1], qf[ks], bf[2], bf[3]);
            }
        }

        // ---- online softmax in exp2 domain ----
        #pragma unroll
        for (int ni = 0; ni < 8; ni++)
            #pragma unroll
            for (int j = 0; j < 4; j++) s[ni][j] *= SC_L2E;

        float mx0 = -1e30f, mx1 = -1e30f;
        #pragma unroll
        for (int ni = 0; ni < 8; ni++) {
            mx0 = fmaxf(mx0, fmaxf(s[ni][0], s[ni][1]));
            mx1 = fmaxf(mx1, fmaxf(s[ni][2], s[ni][3]));
        }
        mx0 = fmaxf(mx0, __shfl_xor_sync(0xffffffffu, mx0, 1));
        mx0 = fmaxf(mx0, __shfl_xor_sync(0xffffffffu, mx0, 2));
        mx1 = fmaxf(mx1, __shfl_xor_sync(0xffffffffu, mx1, 1));
        mx1 = fmaxf(mx1, __shfl_xor_sync(0xffffffffu, mx1, 2));

        const float mn0 = fmaxf(mrow[0], mx0);
        const float mn1 = fmaxf(mrow[1], mx1);
        const float al0 = ex2(mrow[0] - mn0);
        const float al1 = ex2(mrow[1] - mn1);
        mrow[0] = mn0; mrow[1] = mn1;

        float sum0 = 0.f, sum1 = 0.f;
        #pragma unroll
        for (int ni = 0; ni < 8; ni++) {
            s[ni][0] = ex2(s[ni][0] - mn0); sum0 += s[ni][0];
            s[ni][1] = ex2(s[ni][1] - mn0); sum0 += s[ni][1];
            s[ni][2] = ex2(s[ni][2] - mn1); sum1 += s[ni][2];
            s[ni][3] = ex2(s[ni][3] - mn1); sum1 += s[ni][3];
        }
        sum0 += __shfl_xor_sync(0xffffffffu, sum0, 1);
        sum0 += __shfl_xor_sync(0xffffffffu, sum0, 2);
        sum1 += __shfl_xor_sync(0xffffffffu, sum1, 1);
        sum1 += __shfl_xor_sync(0xffffffffu, sum1, 2);
        lrow[0] = lrow[0] * al0 + sum0;
        lrow[1] = lrow[1] * al1 + sum1;

        if (__any_sync(0xffffffffu, (al0 != 1.f) | (al1 != 1.f))) {
            #pragma unroll
            for (int ni = 0; ni < 8; ni++) {
                o[ni][0] *= al0; o[ni][1] *= al0;
                o[ni][2] *= al1; o[ni][3] *= al1;
            }
        }

        // ---- O += P @ V : P A-fragments packed directly from S C-frags ----
        #pragma unroll
        for (int ks = 0; ks < 4; ks++) {
            uint32_t pf[4];
            asm("cvt.rn.f16x2.f32 %0, %1, %2;" : "=r"(pf[0])
                : "f"(s[2 * ks][1]),     "f"(s[2 * ks][0]));
            asm("cvt.rn.f16x2.f32 %0, %1, %2;" : "=r"(pf[1])
                : "f"(s[2 * ks][3]),     "f"(s[2 * ks][2]));
            asm("cvt.rn.f16x2.f32 %0, %1, %2;" : "=r"(pf[2])
                : "f"(s[2 * ks + 1][1]), "f"(s[2 * ks + 1][0]));
            asm("cvt.rn.f16x2.f32 %0, %1, %2;" : "=r"(pf[3])
                : "f"(s[2 * ks + 1][3]), "f"(s[2 * ks + 1][2]));
            #pragma unroll
            for (int np = 0; np < 4; np++) {
                uint32_t vf[4];
                const uint32_t vd = v_u[buf] +
                    (uint32_t)((ks * 16 + (lane & 7) + (((lane >> 3) & 1) << 3)) * FSTR
                               + np * 16 + ((lane >> 4) << 3)) * 2;
                ldm4t(vf, vd);
                mma16(o[2 * np],     pf, vf[0], vf[1]);
                mma16(o[2 * np + 1], pf, vf[2], vf[3]);
            }
        }
        __syncthreads();
    }

    const float inv0 = 1.f / lrow[0];
    const float inv1 = 1.f / lrow[1];
    const size_t n0 = (size_t)bb * SEQ + qt * 64 + m0 + qr;
    #pragma unroll
    for (int ni = 0; ni < 8; ni++) {
        const int c = h * DHEAD + ni * 8 + 2 * qc;
        *(__half2*)(out + n0 * INNER + c) =
            __floats2half2_rn(o[ni][0] * inv0, o[ni][1] * inv0);
        *(__half2*)(out + (n0 + 8) * INNER + c) =
            __floats2half2_rn(o[ni][2] * inv1, o[ni][3] * inv1);
    }
}

// ---------------------------------------------------------------------------
extern "C" void kernel_launch(void* const* d_in, const int* in_sizes, int n_in,
                              void* d_out, int out_size)
{
    const float* x     = (const float*)d_in[0];
    const float* ln_g  = (const float*)d_in[1];
    const float* ln_b  = (const float*)d_in[2];
    const float* W_qkv = (const float*)d_in[3];
    const float* b_qkv = (const float*)d_in[4];
    const float* W_out = (const float*)d_in[5];
    const float* b_out = (const float*)d_in[6];
    float* out = (float*)d_out;

    __half *xn, *qkv, *attn, *wtq, *wto;
    cudaGetSymbolAddress((void**)&xn,   g_xn);
    cudaGetSymbolAddress((void**)&qkv,  g_qkv);
    cudaGetSymbolAddress((void**)&attn, g_attn);
    cudaGetSymbolAddress((void**)&wtq,  g_wtq);
    cudaGetSymbolAddress((void**)&wto,  g_wto);

    const int flash_smem = 5 * 64 * FSTR * (int)sizeof(__half);  // 46080
    cudaFuncSetAttribute(gemm_h, cudaFuncAttributeMaxDynamicSharedMemorySize,
                         G2_SMEM);
    cudaFuncSetAttribute(gemm_o, cudaFuncAttributeMaxDynamicSharedMemorySize,
                         GO_SMEM);
    cudaFuncSetAttribute(flash_h, cudaFuncAttributeMaxDynamicSharedMemorySize,
                         flash_smem);

    // 0) fused prep: both weight transposes + LayerNorm, one launch
    prep_kernel<<<PREP_BLKS, 256>>>(W_qkv, wtq, W_out, wto,
                                    x, ln_g, ln_b, xn);

    // 1) QKV projection (fp16 mma, 256x128 tiles, BK=64, half out)
    gemm_h<<<dim3(QKV_N / 128, ROWS / 256), 256, G2_SMEM>>>(
        xn, wtq, b_qkv, qkv, QKV_N, DIM);

    // 2) attention (fp16 flash, register-resident P, half out)
    flash_h<<<dim3(SEQ / 64, BATCH * HEADS), 128, flash_smem>>>(qkv, attn);

    // 3) output projection (fp16 mma, 128x128 tiles, BK=64, fp32 out)
    gemm_o<<<dim3(DIM / 128, ROWS / 128), 256, GO_SMEM>>>(
        attn, wto, b_out, out, DIM, INNER);
}